// round 13
// baseline (speedup 1.0000x reference)
#include <cuda_runtime.h>
#include <cuda_bf16.h>
#include <cstdint>

#define NN 50000
#define EE 800000
#define FD 128           // hidden = heads*C = 2*64
#define NEG 0.2f
#define BN_EPS 1e-5f

// ---------------- scratch (device globals; referenced ONLY inside kernels) ----
__device__ __align__(16) float  g_h[NN * FD];    // per-layer features (GEMM out)
__device__ __align__(16) float  g_agg[NN * FD];  // GAT aggregate output (pre-BN)
__device__ __align__(16) uint32_t g_wtf[2][FD * FD];  // W tf32 (rna) bits per layer
__device__ float2 g_asrc[NN];
__device__ float2 g_adst[NN];
__device__ int    g_counts[NN];
__device__ int    g_cursor[NN];
__device__ int    g_offsets[NN + 1];
__device__ int    g_srt[EE];
__device__ double g_bnsum[2][FD];
__device__ double g_bnsq[2][FD];
__device__ unsigned int g_gmax[2][2];   // [layer][head]: encoded global max of asrc

__device__ __forceinline__ int clampN(int v) {
    return v < 0 ? 0 : (v >= NN ? NN - 1 : v);
}
__device__ __forceinline__ float lrelu(float v) { return v > 0.f ? v : NEG * v; }

// monotone float<->uint encoding for atomicMax
__device__ __forceinline__ unsigned int encf(float f) {
    unsigned int u = __float_as_uint(f);
    return (u & 0x80000000u) ? ~u : (u | 0x80000000u);
}
__device__ __forceinline__ float decf(unsigned int u) {
    return __uint_as_float((u & 0x80000000u) ? (u ^ 0x80000000u) : ~u);
}

__device__ __forceinline__ uint32_t f2tf32(float f) {
    uint32_t r;
    asm("cvt.rna.tf32.f32 %0, %1;" : "=r"(r) : "f"(f));
    return r;
}

#define MMA_TF32(d, a, b0, b1) \
    asm volatile("mma.sync.aligned.m16n8k8.row.col.f32.tf32.tf32.f32 " \
        "{%0,%1,%2,%3}, {%4,%5,%6,%7}, {%8,%9}, {%0,%1,%2,%3};" \
        : "+f"((d)[0]), "+f"((d)[1]), "+f"((d)[2]), "+f"((d)[3]) \
        : "r"((a)[0]), "r"((a)[1]), "r"((a)[2]), "r"((a)[3]), \
          "r"(b0), "r"(b1))

// -------- prep: zero counters/stats + precompute W tf32 (both layers) ---------
__global__ void k_prep(const float* __restrict__ W1, const float* __restrict__ W2) {
    int i = blockIdx.x * blockDim.x + threadIdx.x;
    if (i < NN) g_counts[i] = 0;
    if (i < FD) {
        g_bnsum[0][i] = 0.0; g_bnsq[0][i] = 0.0;
        g_bnsum[1][i] = 0.0; g_bnsq[1][i] = 0.0;
    }
    if (i < 4) g_gmax[i >> 1][i & 1] = 0u;
    if (i < FD * FD) {
        g_wtf[0][i] = f2tf32(W1[i]);
        g_wtf[1][i] = f2tf32(W2[i]);
    }
}

// ---------------- counting sort by destination --------------------------------
__global__ void k_hist(const int* __restrict__ dst) {
    int e4 = blockIdx.x * blockDim.x + threadIdx.x;
    if (e4 < EE / 4) {
        int4 d = ((const int4*)dst)[e4];
        atomicAdd(&g_counts[clampN(d.x)], 1);
        atomicAdd(&g_counts[clampN(d.y)], 1);
        atomicAdd(&g_counts[clampN(d.z)], 1);
        atomicAdd(&g_counts[clampN(d.w)], 1);
    }
}

__global__ void k_scan() {
    __shared__ int ssum[1024];
    const int CH = (NN + 1023) / 1024;
    int t = threadIdx.x;
    int base = t * CH;
    int s = 0;
    for (int i = 0; i < CH; i++) {
        int idx = base + i;
        if (idx < NN) s += g_counts[idx];
    }
    ssum[t] = s;
    __syncthreads();
    for (int o = 1; o < 1024; o <<= 1) {
        int u = (t >= o) ? ssum[t - o] : 0;
        __syncthreads();
        ssum[t] += u;
        __syncthreads();
    }
    int off = ssum[t] - s;
    for (int i = 0; i < CH; i++) {
        int idx = base + i;
        if (idx < NN) {
            g_offsets[idx] = off;
            g_cursor[idx]  = off;
            off += g_counts[idx];
        }
    }
    if (t == 0) g_offsets[NN] = EE;
}

__global__ void k_scatter(const int* __restrict__ src,
                          const int* __restrict__ dst) {
    int e4 = blockIdx.x * blockDim.x + threadIdx.x;
    if (e4 < EE / 4) {
        int4 d = ((const int4*)dst)[e4];
        int4 s = ((const int4*)src)[e4];
        int p;
        p = atomicAdd(&g_cursor[clampN(d.x)], 1); if (p >= 0 && p < EE) g_srt[p] = clampN(s.x);
        p = atomicAdd(&g_cursor[clampN(d.y)], 1); if (p >= 0 && p < EE) g_srt[p] = clampN(s.y);
        p = atomicAdd(&g_cursor[clampN(d.z)], 1); if (p >= 0 && p < EE) g_srt[p] = clampN(s.z);
        p = atomicAdd(&g_cursor[clampN(d.w)], 1); if (p >= 0 && p < EE) g_srt[p] = clampN(s.w);
    }
}

// ============== 2xTF32 (exact-A split) mma.sync GEMM + attention epilogue =====
// A = Ahi(mask) + Alo(tf32 of exact residual)  ->  A error ~2^-24.
// B = single rna tf32 (preconverted)           ->  dominant error ~1.2e-4 rel.
#define ASTR 20    // A row stride (conflict-free fragment access)
#define BSTR 136   // B k-row stride; 136 % 32 == 8 -> conflict-free
#define TF32_MASK 0xFFFFE000u

__global__ void k_gemm_mma(const float* __restrict__ X,
                           const float* __restrict__ gamma, const float* __restrict__ beta,
                           const float* __restrict__ att_s, const float* __restrict__ att_d,
                           int mode) {
    __shared__ uint32_t sAhi[128 * ASTR];
    __shared__ uint32_t sAlo[128 * ASTR];
    __shared__ uint32_t sB[16 * BSTR];
    __shared__ float s_atts[FD], s_attd[FD], s_bnA[FD], s_bnB[FD];
    __shared__ unsigned int s_m0, s_m1;

    int t = threadIdx.x;
    int rb = blockIdx.x * 128;

    if (t == 0) { s_m0 = 0u; s_m1 = 0u; }
    if (t < FD) {
        s_atts[t] = att_s[t];
        s_attd[t] = att_d[t];
        if (mode) {
            double mean = g_bnsum[0][t] / (double)NN;
            double var  = g_bnsq[0][t] / (double)NN - mean * mean;
            float a = gamma[t] * rsqrtf((float)var + BN_EPS);
            s_bnA[t] = a;
            s_bnB[t] = beta[t] - (float)mean * a;
        }
    }

    int lane = t & 31, warp = t >> 5;
    int g  = lane >> 2;       // groupID (row within fragment)
    int t4 = lane & 3;        // threadID in group
    int wr = warp * 16;       // warp row base within tile

    float d[16][4];
    #pragma unroll
    for (int nt = 0; nt < 16; nt++) {
        d[nt][0] = 0.f; d[nt][1] = 0.f; d[nt][2] = 0.f; d[nt][3] = 0.f;
    }

    const float4* X4 = (const float4*)(mode ? (const float*)g_agg : X);
    const uint4* Wt4 = (const uint4*)g_wtf[mode];

    for (int kc = 0; kc < 8; kc++) {
        __syncthreads();

        // --- stage A chunk: exact 2-term split (mask hi + tf32 residual) ---
        #pragma unroll
        for (int j = 0; j < 2; j++) {
            int idx = t + j * 256;
            int row = idx >> 2, c4 = idx & 3;
            int grow = rb + row;
            float4 v = (grow < NN) ? X4[grow * 32 + kc * 4 + c4]
                                   : make_float4(0.f, 0.f, 0.f, 0.f);
            float vv[4] = {v.x, v.y, v.z, v.w};
            int sbase = row * ASTR + c4 * 4;
            #pragma unroll
            for (int i = 0; i < 4; i++) {
                float val = vv[i];
                if (mode) {
                    int c = kc * 16 + c4 * 4 + i;
                    float y = s_bnA[c] * val + s_bnB[c];
                    val = y > 0.f ? y : expm1f(y);
                }
                uint32_t hb = __float_as_uint(val) & TF32_MASK;
                float lof = val - __uint_as_float(hb);   // exact Dekker residual
                sAhi[sbase + i] = hb;
                sAlo[sbase + i] = f2tf32(lof);
            }
        }

        // --- stage B chunk: pure copy of preconverted bits ---
        {
            int idx = t;                    // 256 threads cover 512 uint4 in 2 steps
            #pragma unroll
            for (int j = 0; j < 2; j++) {
                int k = idx >> 5, c4 = idx & 31;
                uint4 h = Wt4[(kc * 16 + k) * 32 + c4];
                int sbase = k * BSTR + c4 * 4;
                sB[sbase + 0] = h.x; sB[sbase + 1] = h.y;
                sB[sbase + 2] = h.z; sB[sbase + 3] = h.w;
                idx += 256;
            }
        }
        __syncthreads();

        #pragma unroll
        for (int ks = 0; ks < 2; ks++) {
            int kk = ks * 8;
            uint32_t ahi[4], alo[4];
            int ab = (wr + g) * ASTR + kk;
            ahi[0] = sAhi[ab + t4];
            ahi[1] = sAhi[ab + 8 * ASTR + t4];
            ahi[2] = sAhi[ab + t4 + 4];
            ahi[3] = sAhi[ab + 8 * ASTR + t4 + 4];
            alo[0] = sAlo[ab + t4];
            alo[1] = sAlo[ab + 8 * ASTR + t4];
            alo[2] = sAlo[ab + t4 + 4];
            alo[3] = sAlo[ab + 8 * ASTR + t4 + 4];
            #pragma unroll
            for (int nt = 0; nt < 16; nt++) {
                int bcol = nt * 8 + g;
                uint32_t b0 = sB[(kk + t4) * BSTR + bcol];
                uint32_t b1 = sB[(kk + t4 + 4) * BSTR + bcol];
                MMA_TF32(d[nt], ahi, b0, b1);
                MMA_TF32(d[nt], alo, b0, b1);
            }
        }
    }

    // --- epilogue: store h, attention dots per head, block max of asrc ---
    int r0 = rb + wr + g;
    int r1 = r0 + 8;
    float ds0h0 = 0.f, ds0h1 = 0.f, dd0h0 = 0.f, dd0h1 = 0.f;
    float ds1h0 = 0.f, ds1h1 = 0.f, dd1h0 = 0.f, dd1h1 = 0.f;
    #pragma unroll
    for (int nt = 0; nt < 16; nt++) {
        int c0 = nt * 8 + t4 * 2;
        float a0 = s_atts[c0], a1 = s_atts[c0 + 1];
        float b0 = s_attd[c0], b1 = s_attd[c0 + 1];
        float p0 = d[nt][0] * a0 + d[nt][1] * a1;
        float q0 = d[nt][0] * b0 + d[nt][1] * b1;
        float p1 = d[nt][2] * a0 + d[nt][3] * a1;
        float q1 = d[nt][2] * b0 + d[nt][3] * b1;
        if (nt < 8) { ds0h0 += p0; dd0h0 += q0; ds1h0 += p1; dd1h0 += q1; }
        else        { ds0h1 += p0; dd0h1 += q0; ds1h1 += p1; dd1h1 += q1; }
        if (r0 < NN) *(float2*)&g_h[r0 * FD + c0] = make_float2(d[nt][0], d[nt][1]);
        if (r1 < NN) *(float2*)&g_h[r1 * FD + c0] = make_float2(d[nt][2], d[nt][3]);
    }
    #pragma unroll
    for (int o = 1; o <= 2; o <<= 1) {
        ds0h0 += __shfl_xor_sync(0xFFFFFFFFu, ds0h0, o);
        ds0h1 += __shfl_xor_sync(0xFFFFFFFFu, ds0h1, o);
        dd0h0 += __shfl_xor_sync(0xFFFFFFFFu, dd0h0, o);
        dd0h1 += __shfl_xor_sync(0xFFFFFFFFu, dd0h1, o);
        ds1h0 += __shfl_xor_sync(0xFFFFFFFFu, ds1h0, o);
        ds1h1 += __shfl_xor_sync(0xFFFFFFFFu, ds1h1, o);
        dd1h0 += __shfl_xor_sync(0xFFFFFFFFu, dd1h0, o);
        dd1h1 += __shfl_xor_sync(0xFFFFFFFFu, dd1h1, o);
    }
    if (t4 == 0) {
        if (r0 < NN) {
            g_asrc[r0] = make_float2(ds0h0, ds0h1);
            g_adst[r0] = make_float2(dd0h0, dd0h1);
            atomicMax(&s_m0, encf(ds0h0));
            atomicMax(&s_m1, encf(ds0h1));
        }
        if (r1 < NN) {
            g_asrc[r1] = make_float2(ds1h0, ds1h1);
            g_adst[r1] = make_float2(dd1h0, dd1h1);
            atomicMax(&s_m0, encf(ds1h0));
            atomicMax(&s_m1, encf(ds1h1));
        }
    }
    __syncthreads();
    if (t == 0) {
        atomicMax(&g_gmax[mode][0], s_m0);
        atomicMax(&g_gmax[mode][1], s_m1);
    }
}

// ----- warp-per-dst aggregation: global-max softmax, quad-MLP gather ---------
__global__ void k_agg(const float* __restrict__ bias, int slot) {
    __shared__ int   s_src[8][64];
    __shared__ float s_a0[8][64];
    __shared__ float s_a1[8][64];
    int wb   = threadIdx.x >> 5;
    int lane = threadIdx.x & 31;
    int w = (blockIdx.x * blockDim.x + threadIdx.x) >> 5;
    if (w >= NN) return;
    int start = g_offsets[w];
    int deg   = g_offsets[w + 1] - start;

    float2 ad    = g_adst[w];
    float2 aself = g_asrc[w];
    float m0 = lrelu(decf(g_gmax[slot][0]) + ad.x);
    float m1 = lrelu(decf(g_gmax[slot][1]) + ad.y);

    // single pass: gather asrc, exp, stage (first 64 edges), accumulate sums
    float s0 = 0.f, s1 = 0.f;
    #pragma unroll
    for (int it = 0; it < 2; it++) {
        int j = it * 32 + lane;
        bool have = j < deg;
        int sj = 0;
        float x0 = 0.f, x1 = 0.f;
        if (have) {
            sj = g_srt[start + j];
            float2 a = g_asrc[sj];
            x0 = __expf(lrelu(a.x + ad.x) - m0);
            x1 = __expf(lrelu(a.y + ad.y) - m1);
        }
        s_src[wb][it * 32 + lane] = sj;
        s_a0[wb][it * 32 + lane] = x0;
        s_a1[wb][it * 32 + lane] = x1;
        s0 += x0; s1 += x1;
    }
    for (int j = 64 + lane; j < deg; j += 32) {   // astronomically rare tail
        float2 a = g_asrc[g_srt[start + j]];
        s0 += __expf(lrelu(a.x + ad.x) - m0);
        s1 += __expf(lrelu(a.y + ad.y) - m1);
    }
    #pragma unroll
    for (int o = 16; o; o >>= 1) {
        s0 += __shfl_xor_sync(0xFFFFFFFFu, s0, o);
        s1 += __shfl_xor_sync(0xFFFFFFFFu, s1, o);
    }
    float xs0 = __expf(lrelu(aself.x + ad.x) - m0);
    float xs1 = __expf(lrelu(aself.y + ad.y) - m1);
    s0 += xs0; s1 += xs1;
    float inv0 = 1.f / (s0 + 1e-16f);
    float inv1 = 1.f / (s1 + 1e-16f);

    // normalize own staged entries (lane-local), then make visible
    s_a0[wb][lane]      *= inv0;
    s_a0[wb][lane + 32] *= inv0;
    s_a1[wb][lane]      *= inv1;
    s_a1[wb][lane + 32] *= inv1;
    __syncwarp();

    int head = lane >> 4;
    const float4* H4 = (const float4*)g_h;

    float salpha = head ? xs1 * inv1 : xs0 * inv0;
    float4 hv = H4[w * 32 + lane];
    float4 acc0 = make_float4(salpha * hv.x, salpha * hv.y, salpha * hv.z, salpha * hv.w);
    float4 acc1 = make_float4(0.f, 0.f, 0.f, 0.f);
    float4 acc2 = make_float4(0.f, 0.f, 0.f, 0.f);
    float4 acc3 = make_float4(0.f, 0.f, 0.f, 0.f);

    const float* sal = head ? s_a1[wb] : s_a0[wb];
    int nd = deg < 64 ? deg : 64;
    int j = 0;
    for (; j + 3 < nd; j += 4) {     // quad accumulators -> 4x load MLP
        int i0 = s_src[wb][j],     i1 = s_src[wb][j + 1];
        int i2 = s_src[wb][j + 2], i3 = s_src[wb][j + 3];
        float a0 = sal[j],     a1 = sal[j + 1];
        float a2 = sal[j + 2], a3 = sal[j + 3];
        float4 v0 = H4[i0 * 32 + lane];
        float4 v1 = H4[i1 * 32 + lane];
        float4 v2 = H4[i2 * 32 + lane];
        float4 v3 = H4[i3 * 32 + lane];
        acc0.x += a0 * v0.x; acc0.y += a0 * v0.y; acc0.z += a0 * v0.z; acc0.w += a0 * v0.w;
        acc1.x += a1 * v1.x; acc1.y += a1 * v1.y; acc1.z += a1 * v1.z; acc1.w += a1 * v1.w;
        acc2.x += a2 * v2.x; acc2.y += a2 * v2.y; acc2.z += a2 * v2.z; acc2.w += a2 * v2.w;
        acc3.x += a3 * v3.x; acc3.y += a3 * v3.y; acc3.z += a3 * v3.z; acc3.w += a3 * v3.w;
    }
    for (; j < nd; j++) {
        int sa = s_src[wb][j];
        float aa = sal[j];
        float4 va = H4[sa * 32 + lane];
        acc0.x += aa * va.x; acc0.y += aa * va.y; acc0.z += aa * va.z; acc0.w += aa * va.w;
    }
    acc0.x += acc1.x + acc2.x + acc3.x;
    acc0.y += acc1.y + acc2.y + acc3.y;
    acc0.z += acc1.z + acc2.z + acc3.z;
    acc0.w += acc1.w + acc2.w + acc3.w;

    for (int jj = 64; jj < deg; jj++) {   // rare tail: recompute alpha inline
        int srcj = g_srt[start + jj];
        float2 a = g_asrc[srcj];
        float e = head ? (lrelu(a.y + ad.y) - m1) : (lrelu(a.x + ad.x) - m0);
        float alpha = __expf(e) * (head ? inv1 : inv0);
        float4 v = H4[srcj * 32 + lane];
        acc0.x += alpha * v.x;
        acc0.y += alpha * v.y;
        acc0.z += alpha * v.z;
        acc0.w += alpha * v.w;
    }

    float4 b = ((const float4*)bias)[lane];
    acc0.x += b.x; acc0.y += b.y; acc0.z += b.z; acc0.w += b.w;
    ((float4*)g_agg)[w * 32 + lane] = acc0;
}

// ---------------- batch norm stats + final apply ------------------------------
__global__ void k_bnstats(int slot) {
    int c = threadIdx.x & 127;
    int g = threadIdx.x >> 7;
    float sum = 0.f, sq = 0.f;
    for (int r = blockIdx.x * 2 + g; r < NN; r += gridDim.x * 2) {
        float v = g_agg[r * FD + c];
        sum += v;
        sq = fmaf(v, v, sq);
    }
    atomicAdd(&g_bnsum[slot][c], (double)sum);
    atomicAdd(&g_bnsq[slot][c],  (double)sq);
}

__global__ void k_bnapply(const float* __restrict__ gamma,
                          const float* __restrict__ beta,
                          float* __restrict__ out) {
    int i = blockIdx.x * blockDim.x + threadIdx.x;
    if (i >= NN * 32) return;
    int c4 = (i & 31) * 4;
    float4 v  = ((const float4*)g_agg)[i];
    float4 gm = ((const float4*)gamma)[i & 31];
    float4 bt = ((const float4*)beta)[i & 31];
    float res[4];
    float vin[4] = {v.x, v.y, v.z, v.w};
    float gs[4]  = {gm.x, gm.y, gm.z, gm.w};
    float bs[4]  = {bt.x, bt.y, bt.z, bt.w};
    #pragma unroll
    for (int k = 0; k < 4; k++) {
        int c = c4 + k;
        float mean = (float)(g_bnsum[1][c] / (double)NN);
        float var  = (float)(g_bnsq[1][c] / (double)NN) - mean * mean;
        float is   = rsqrtf(var + BN_EPS);
        float y = (vin[k] - mean) * is * gs[k] + bs[k];
        res[k] = y > 0.f ? y : expm1f(y);
    }
    ((float4*)out)[i] = make_float4(res[0], res[1], res[2], res[3]);
}

// ---------------- launch: kernel launches ONLY (graph-capture safe) -----------
extern "C" void kernel_launch(void* const* d_in, const int* in_sizes, int n_in,
                              void* d_out, int out_size) {
    const float* x        = (const float*)d_in[0];
    const int*   eidx     = (const int*)d_in[1];
    const float* W1       = (const float*)d_in[2];
    const float* att_src1 = (const float*)d_in[3];
    const float* att_dst1 = (const float*)d_in[4];
    const float* b1       = (const float*)d_in[5];
    const float* W2       = (const float*)d_in[6];
    const float* att_src2 = (const float*)d_in[7];
    const float* att_dst2 = (const float*)d_in[8];
    const float* b2       = (const float*)d_in[9];
    const float* g1       = (const float*)d_in[10];
    const float* be1      = (const float*)d_in[11];
    const float* g2       = (const float*)d_in[12];
    const float* be2      = (const float*)d_in[13];
    float* out = (float*)d_out;

    const int* esrc = eidx;
    const int* edst = eidx + EE;

    const int WARP_BLOCKS = NN / 8;                 // 6250
    const int MMA_BLOCKS  = (NN + 127) / 128;       // 391
    const int E4_BLOCKS   = (EE / 4 + 255) / 256;

    k_prep<<<(NN + 255) / 256, 256>>>(W1, W2);
    k_hist<<<E4_BLOCKS, 256>>>(edst);
    k_scan<<<1, 1024>>>();
    k_scatter<<<E4_BLOCKS, 256>>>(esrc, edst);

    // --- layer 1 ---
    k_gemm_mma<<<MMA_BLOCKS, 256>>>(x, g1, be1, att_src1, att_dst1, 0);
    k_agg<<<WARP_BLOCKS, 256>>>(b1, 0);
    k_bnstats<<<256, 256>>>(0);

    // --- layer 2 (BN+ELU of layer 1 fused into A-load) ---
    k_gemm_mma<<<MMA_BLOCKS, 256>>>(x, g2, be2, att_src2, att_dst2, 1);
    k_agg<<<WARP_BLOCKS, 256>>>(b2, 1);
    k_bnstats<<<256, 256>>>(1);
    k_bnapply<<<WARP_BLOCKS, 256>>>(g2, be2, out);
}

// round 14
// speedup vs baseline: 1.2023x; 1.2023x over previous
#include <cuda_runtime.h>
#include <cuda_fp16.h>
#include <cstdint>

#define NN 50000
#define EE 800000
#define FD 128           // hidden = heads*C = 2*64
#define NEG 0.2f
#define BN_EPS 1e-5f

// ---------------- scratch (device globals; referenced ONLY inside kernels) ----
__device__ __align__(16) uint32_t g_h2[NN * 64];      // h in half2 (ch 2i,2i+1)
__device__ __align__(16) float    g_agg[NN * FD];     // GAT aggregate (pre-BN)
__device__ __align__(16) uint32_t g_whi[2][FD * FD];  // W tf32-hi bits per layer
__device__ __align__(16) uint32_t g_wlo[2][FD * FD];  // W tf32-lo bits per layer
__device__ float2 g_asrc[NN];
__device__ float2 g_adst[NN];
__device__ int    g_counts[NN];
__device__ int    g_cursor[NN];
__device__ int    g_offsets[NN + 1];
__device__ int    g_srt[EE];
__device__ float  g_bnsum[2][FD];
__device__ float  g_bnsq[2][FD];
__device__ unsigned int g_gmax[2][2];   // [layer][head]: encoded global max of asrc

__device__ __forceinline__ int clampN(int v) {
    return v < 0 ? 0 : (v >= NN ? NN - 1 : v);
}
__device__ __forceinline__ float lrelu(float v) { return v > 0.f ? v : NEG * v; }

// monotone float<->uint encoding for atomicMax
__device__ __forceinline__ unsigned int encf(float f) {
    unsigned int u = __float_as_uint(f);
    return (u & 0x80000000u) ? ~u : (u | 0x80000000u);
}
__device__ __forceinline__ float decf(unsigned int u) {
    return __uint_as_float((u & 0x80000000u) ? (u ^ 0x80000000u) : ~u);
}

__device__ __forceinline__ uint32_t f2tf32(float f) {
    uint32_t r;
    asm("cvt.rna.tf32.f32 %0, %1;" : "=r"(r) : "f"(f));
    return r;
}

#define MMA_TF32(d, a, b0, b1) \
    asm volatile("mma.sync.aligned.m16n8k8.row.col.f32.tf32.tf32.f32 " \
        "{%0,%1,%2,%3}, {%4,%5,%6,%7}, {%8,%9}, {%0,%1,%2,%3};" \
        : "+f"((d)[0]), "+f"((d)[1]), "+f"((d)[2]), "+f"((d)[3]) \
        : "r"((a)[0]), "r"((a)[1]), "r"((a)[2]), "r"((a)[3]), \
          "r"(b0), "r"(b1))

// -------- prep: zero counters/stats + precompute W tf32 hi/lo (both layers) ---
__global__ void k_prep(const float* __restrict__ W1, const float* __restrict__ W2) {
    int i = blockIdx.x * blockDim.x + threadIdx.x;
    if (i < NN) g_counts[i] = 0;
    if (i < FD) {
        g_bnsum[0][i] = 0.f; g_bnsq[0][i] = 0.f;
        g_bnsum[1][i] = 0.f; g_bnsq[1][i] = 0.f;
    }
    if (i < 4) g_gmax[i >> 1][i & 1] = 0u;
    if (i < FD * FD) {
        #pragma unroll
        for (int l = 0; l < 2; l++) {
            float w = (l ? W2 : W1)[i];
            uint32_t hb = f2tf32(w);
            float lof = w - __uint_as_float(hb);
            g_whi[l][i] = hb;
            g_wlo[l][i] = f2tf32(lof);
        }
    }
}

// ---------------- counting sort by destination --------------------------------
__global__ void k_hist(const int* __restrict__ dst) {
    int e4 = blockIdx.x * blockDim.x + threadIdx.x;
    if (e4 < EE / 4) {
        int4 d = ((const int4*)dst)[e4];
        atomicAdd(&g_counts[clampN(d.x)], 1);
        atomicAdd(&g_counts[clampN(d.y)], 1);
        atomicAdd(&g_counts[clampN(d.z)], 1);
        atomicAdd(&g_counts[clampN(d.w)], 1);
    }
}

__global__ void k_scan() {
    __shared__ int ssum[1024];
    const int CH = (NN + 1023) / 1024;
    int t = threadIdx.x;
    int base = t * CH;
    int s = 0;
    for (int i = 0; i < CH; i++) {
        int idx = base + i;
        if (idx < NN) s += g_counts[idx];
    }
    ssum[t] = s;
    __syncthreads();
    for (int o = 1; o < 1024; o <<= 1) {
        int u = (t >= o) ? ssum[t - o] : 0;
        __syncthreads();
        ssum[t] += u;
        __syncthreads();
    }
    int off = ssum[t] - s;
    for (int i = 0; i < CH; i++) {
        int idx = base + i;
        if (idx < NN) {
            g_offsets[idx] = off;
            g_cursor[idx]  = off;
            off += g_counts[idx];
        }
    }
    if (t == 0) g_offsets[NN] = EE;
}

__global__ void k_scatter(const int* __restrict__ src,
                          const int* __restrict__ dst) {
    int e4 = blockIdx.x * blockDim.x + threadIdx.x;
    if (e4 < EE / 4) {
        int4 d = ((const int4*)dst)[e4];
        int4 s = ((const int4*)src)[e4];
        int p;
        p = atomicAdd(&g_cursor[clampN(d.x)], 1); if (p >= 0 && p < EE) g_srt[p] = clampN(s.x);
        p = atomicAdd(&g_cursor[clampN(d.y)], 1); if (p >= 0 && p < EE) g_srt[p] = clampN(s.y);
        p = atomicAdd(&g_cursor[clampN(d.z)], 1); if (p >= 0 && p < EE) g_srt[p] = clampN(s.z);
        p = atomicAdd(&g_cursor[clampN(d.w)], 1); if (p >= 0 && p < EE) g_srt[p] = clampN(s.w);
    }
}

// ============== 3xTF32 mma.sync GEMM + attention-score epilogue ==============
// h stored to fp16 (half2) -> halves the aggregation gather traffic.
#define ASTR 20    // A row stride (conflict-free fragment access)
#define BSTR 136   // B k-row stride; 136 % 32 == 8 -> conflict-free
#define TF32_MASK 0xFFFFE000u

__global__ void k_gemm_mma(const float* __restrict__ X,
                           const float* __restrict__ gamma, const float* __restrict__ beta,
                           const float* __restrict__ att_s, const float* __restrict__ att_d,
                           int mode) {
    __shared__ uint32_t sAhi[128 * ASTR];
    __shared__ uint32_t sAlo[128 * ASTR];
    __shared__ uint32_t sBhi[16 * BSTR];
    __shared__ uint32_t sBlo[16 * BSTR];
    __shared__ float s_atts[FD], s_attd[FD], s_bnA[FD], s_bnB[FD];
    __shared__ unsigned int s_m0, s_m1;

    int t = threadIdx.x;
    int rb = blockIdx.x * 128;

    if (t == 0) { s_m0 = 0u; s_m1 = 0u; }
    if (t < FD) {
        s_atts[t] = att_s[t];
        s_attd[t] = att_d[t];
        if (mode) {
            float mean = g_bnsum[0][t] * (1.f / NN);
            float var  = g_bnsq[0][t] * (1.f / NN) - mean * mean;
            float a = gamma[t] * rsqrtf(var + BN_EPS);
            s_bnA[t] = a;
            s_bnB[t] = beta[t] - mean * a;
        }
    }

    int lane = t & 31, warp = t >> 5;
    int g  = lane >> 2;       // groupID (row within fragment)
    int t4 = lane & 3;        // threadID in group
    int wr = warp * 16;       // warp row base within tile

    float d[16][4];
    #pragma unroll
    for (int nt = 0; nt < 16; nt++) {
        d[nt][0] = 0.f; d[nt][1] = 0.f; d[nt][2] = 0.f; d[nt][3] = 0.f;
    }

    const float4* X4 = (const float4*)(mode ? (const float*)g_agg : X);
    const uint4* Whi4 = (const uint4*)g_whi[mode];
    const uint4* Wlo4 = (const uint4*)g_wlo[mode];

    for (int kc = 0; kc < 8; kc++) {
        __syncthreads();

        // --- stage A chunk: mask-based hi + exact residual lo ---
        #pragma unroll
        for (int j = 0; j < 2; j++) {
            int idx = t + j * 256;
            int row = idx >> 2, c4 = idx & 3;
            int grow = rb + row;
            float4 v = (grow < NN) ? X4[grow * 32 + kc * 4 + c4]
                                   : make_float4(0.f, 0.f, 0.f, 0.f);
            float vv[4] = {v.x, v.y, v.z, v.w};
            int sbase = row * ASTR + c4 * 4;
            #pragma unroll
            for (int i = 0; i < 4; i++) {
                float val = vv[i];
                if (mode) {
                    int c = kc * 16 + c4 * 4 + i;
                    float y = s_bnA[c] * val + s_bnB[c];
                    val = y > 0.f ? y : expm1f(y);
                }
                uint32_t hb = __float_as_uint(val) & TF32_MASK;
                float lof = val - __uint_as_float(hb);
                sAhi[sbase + i] = hb;
                sAlo[sbase + i] = __float_as_uint(lof) & TF32_MASK;
            }
        }

        // --- stage B chunk: pure copy of preconverted bits ---
        #pragma unroll
        for (int j = 0; j < 2; j++) {
            int idx = t + j * 256;
            int k = idx >> 5, c4 = idx & 31;
            uint4 h = Whi4[(kc * 16 + k) * 32 + c4];
            uint4 l = Wlo4[(kc * 16 + k) * 32 + c4];
            int sbase = k * BSTR + c4 * 4;
            sBhi[sbase + 0] = h.x; sBhi[sbase + 1] = h.y;
            sBhi[sbase + 2] = h.z; sBhi[sbase + 3] = h.w;
            sBlo[sbase + 0] = l.x; sBlo[sbase + 1] = l.y;
            sBlo[sbase + 2] = l.z; sBlo[sbase + 3] = l.w;
        }
        __syncthreads();

        #pragma unroll
        for (int ks = 0; ks < 2; ks++) {
            int kk = ks * 8;
            uint32_t ahi[4], alo[4];
            int ab = (wr + g) * ASTR + kk;
            ahi[0] = sAhi[ab + t4];
            ahi[1] = sAhi[ab + 8 * ASTR + t4];
            ahi[2] = sAhi[ab + t4 + 4];
            ahi[3] = sAhi[ab + 8 * ASTR + t4 + 4];
            alo[0] = sAlo[ab + t4];
            alo[1] = sAlo[ab + 8 * ASTR + t4];
            alo[2] = sAlo[ab + t4 + 4];
            alo[3] = sAlo[ab + 8 * ASTR + t4 + 4];
            #pragma unroll
            for (int nt = 0; nt < 16; nt++) {
                int bcol = nt * 8 + g;
                uint32_t bh0 = sBhi[(kk + t4) * BSTR + bcol];
                uint32_t bh1 = sBhi[(kk + t4 + 4) * BSTR + bcol];
                uint32_t bl0 = sBlo[(kk + t4) * BSTR + bcol];
                uint32_t bl1 = sBlo[(kk + t4 + 4) * BSTR + bcol];
                MMA_TF32(d[nt], ahi, bh0, bh1);
                MMA_TF32(d[nt], ahi, bl0, bl1);
                MMA_TF32(d[nt], alo, bh0, bh1);
            }
        }
    }

    // --- epilogue: store h (fp16), attention dots, block max of asrc ---
    int r0 = rb + wr + g;
    int r1 = r0 + 8;
    float ds0h0 = 0.f, ds0h1 = 0.f, dd0h0 = 0.f, dd0h1 = 0.f;
    float ds1h0 = 0.f, ds1h1 = 0.f, dd1h0 = 0.f, dd1h1 = 0.f;
    #pragma unroll
    for (int nt = 0; nt < 16; nt++) {
        int c0 = nt * 8 + t4 * 2;
        float a0 = s_atts[c0], a1 = s_atts[c0 + 1];
        float b0 = s_attd[c0], b1 = s_attd[c0 + 1];
        float p0 = d[nt][0] * a0 + d[nt][1] * a1;
        float q0 = d[nt][0] * b0 + d[nt][1] * b1;
        float p1 = d[nt][2] * a0 + d[nt][3] * a1;
        float q1 = d[nt][2] * b0 + d[nt][3] * b1;
        if (nt < 8) { ds0h0 += p0; dd0h0 += q0; ds1h0 += p1; dd1h0 += q1; }
        else        { ds0h1 += p0; dd0h1 += q0; ds1h1 += p1; dd1h1 += q1; }
        if (r0 < NN) {
            __half2 ph = __floats2half2_rn(d[nt][0], d[nt][1]);
            g_h2[r0 * 64 + (c0 >> 1)] = *(uint32_t*)&ph;
        }
        if (r1 < NN) {
            __half2 ph = __floats2half2_rn(d[nt][2], d[nt][3]);
            g_h2[r1 * 64 + (c0 >> 1)] = *(uint32_t*)&ph;
        }
    }
    #pragma unroll
    for (int o = 1; o <= 2; o <<= 1) {
        ds0h0 += __shfl_xor_sync(0xFFFFFFFFu, ds0h0, o);
        ds0h1 += __shfl_xor_sync(0xFFFFFFFFu, ds0h1, o);
        dd0h0 += __shfl_xor_sync(0xFFFFFFFFu, dd0h0, o);
        dd0h1 += __shfl_xor_sync(0xFFFFFFFFu, dd0h1, o);
        ds1h0 += __shfl_xor_sync(0xFFFFFFFFu, ds1h0, o);
        ds1h1 += __shfl_xor_sync(0xFFFFFFFFu, ds1h1, o);
        dd1h0 += __shfl_xor_sync(0xFFFFFFFFu, dd1h0, o);
        dd1h1 += __shfl_xor_sync(0xFFFFFFFFu, dd1h1, o);
    }
    if (t4 == 0) {
        if (r0 < NN) {
            g_asrc[r0] = make_float2(ds0h0, ds0h1);
            g_adst[r0] = make_float2(dd0h0, dd0h1);
            atomicMax(&s_m0, encf(ds0h0));
            atomicMax(&s_m1, encf(ds0h1));
        }
        if (r1 < NN) {
            g_asrc[r1] = make_float2(ds1h0, ds1h1);
            g_adst[r1] = make_float2(dd1h0, dd1h1);
            atomicMax(&s_m0, encf(ds1h0));
            atomicMax(&s_m1, encf(ds1h1));
        }
    }
    __syncthreads();
    if (t == 0) {
        atomicMax(&g_gmax[mode][0], s_m0);
        atomicMax(&g_gmax[mode][1], s_m1);
    }
}

// ----- warp-per-dst aggregation (fp16 h gather) + fused BN statistics --------
// grid is exactly NN/8 blocks x 8 warps: every warp owns one valid node.
__global__ void k_agg(const float* __restrict__ bias, int slot) {
    __shared__ int   s_src[8][64];
    __shared__ float s_a0[8][64];
    __shared__ float s_a1[8][64];
    __shared__ float s_red[8][128];
    int wb   = threadIdx.x >> 5;
    int lane = threadIdx.x & 31;
    int w = (blockIdx.x * blockDim.x + threadIdx.x) >> 5;
    int start = g_offsets[w];
    int deg   = g_offsets[w + 1] - start;

    float2 ad    = g_adst[w];
    float2 aself = g_asrc[w];
    float m0 = lrelu(decf(g_gmax[slot][0]) + ad.x);
    float m1 = lrelu(decf(g_gmax[slot][1]) + ad.y);

    // single pass: gather asrc, exp, stage (first 64 edges), accumulate sums
    float s0 = 0.f, s1 = 0.f;
    #pragma unroll
    for (int it = 0; it < 2; it++) {
        int j = it * 32 + lane;
        bool have = j < deg;
        int sj = 0;
        float x0 = 0.f, x1 = 0.f;
        if (have) {
            sj = g_srt[start + j];
            float2 a = g_asrc[sj];
            x0 = __expf(lrelu(a.x + ad.x) - m0);
            x1 = __expf(lrelu(a.y + ad.y) - m1);
        }
        s_src[wb][it * 32 + lane] = sj;
        s_a0[wb][it * 32 + lane] = x0;
        s_a1[wb][it * 32 + lane] = x1;
        s0 += x0; s1 += x1;
    }
    for (int j = 64 + lane; j < deg; j += 32) {   // astronomically rare tail
        float2 a = g_asrc[g_srt[start + j]];
        s0 += __expf(lrelu(a.x + ad.x) - m0);
        s1 += __expf(lrelu(a.y + ad.y) - m1);
    }
    #pragma unroll
    for (int o = 16; o; o >>= 1) {
        s0 += __shfl_xor_sync(0xFFFFFFFFu, s0, o);
        s1 += __shfl_xor_sync(0xFFFFFFFFu, s1, o);
    }
    float xs0 = __expf(lrelu(aself.x + ad.x) - m0);
    float xs1 = __expf(lrelu(aself.y + ad.y) - m1);
    s0 += xs0; s1 += xs1;
    float inv0 = 1.f / (s0 + 1e-16f);
    float inv1 = 1.f / (s1 + 1e-16f);

    // normalize own staged entries (lane-local), then make visible
    s_a0[wb][lane]      *= inv0;
    s_a0[wb][lane + 32] *= inv0;
    s_a1[wb][lane]      *= inv1;
    s_a1[wb][lane + 32] *= inv1;
    __syncwarp();

    int head = lane >> 4;
    const uint2* H2 = (const uint2*)g_h2;   // H2[row*32+lane] = ch 4l..4l+3

    float salpha = head ? xs1 * inv1 : xs0 * inv0;
    uint2 raw = H2[w * 32 + lane];
    float2 f01 = __half22float2(*(__half2*)&raw.x);
    float2 f23 = __half22float2(*(__half2*)&raw.y);
    float4 acc0 = make_float4(salpha * f01.x, salpha * f01.y,
                              salpha * f23.x, salpha * f23.y);
    float4 acc1 = make_float4(0.f, 0.f, 0.f, 0.f);
    float4 acc2 = make_float4(0.f, 0.f, 0.f, 0.f);
    float4 acc3 = make_float4(0.f, 0.f, 0.f, 0.f);

    const float* sal = head ? s_a1[wb] : s_a0[wb];
    int nd = deg < 64 ? deg : 64;
    int j = 0;
    for (; j + 3 < nd; j += 4) {     // quad accumulators -> 4x load MLP
        int i0 = s_src[wb][j],     i1 = s_src[wb][j + 1];
        int i2 = s_src[wb][j + 2], i3 = s_src[wb][j + 3];
        float a0 = sal[j],     a1 = sal[j + 1];
        float a2 = sal[j + 2], a3 = sal[j + 3];
        uint2 r0 = H2[i0 * 32 + lane];
        uint2 r1 = H2[i1 * 32 + lane];
        uint2 r2 = H2[i2 * 32 + lane];
        uint2 r3 = H2[i3 * 32 + lane];
        float2 p, q;
        p = __half22float2(*(__half2*)&r0.x); q = __half22float2(*(__half2*)&r0.y);
        acc0.x += a0 * p.x; acc0.y += a0 * p.y; acc0.z += a0 * q.x; acc0.w += a0 * q.y;
        p = __half22float2(*(__half2*)&r1.x); q = __half22float2(*(__half2*)&r1.y);
        acc1.x += a1 * p.x; acc1.y += a1 * p.y; acc1.z += a1 * q.x; acc1.w += a1 * q.y;
        p = __half22float2(*(__half2*)&r2.x); q = __half22float2(*(__half2*)&r2.y);
        acc2.x += a2 * p.x; acc2.y += a2 * p.y; acc2.z += a2 * q.x; acc2.w += a2 * q.y;
        p = __half22float2(*(__half2*)&r3.x); q = __half22float2(*(__half2*)&r3.y);
        acc3.x += a3 * p.x; acc3.y += a3 * p.y; acc3.z += a3 * q.x; acc3.w += a3 * q.y;
    }
    for (; j < nd; j++) {
        int sa = s_src[wb][j];
        float aa = sal[j];
        uint2 r = H2[sa * 32 + lane];
        float2 p = __half22float2(*(__half2*)&r.x);
        float2 q = __half22float2(*(__half2*)&r.y);
        acc0.x += aa * p.x; acc0.y += aa * p.y; acc0.z += aa * q.x; acc0.w += aa * q.y;
    }
    acc0.x += acc1.x + acc2.x + acc3.x;
    acc0.y += acc1.y + acc2.y + acc3.y;
    acc0.z += acc1.z + acc2.z + acc3.z;
    acc0.w += acc1.w + acc2.w + acc3.w;

    for (int jj = 64; jj < deg; jj++) {   // rare tail: recompute alpha inline
        int srcj = g_srt[start + jj];
        float2 a = g_asrc[srcj];
        float e = head ? (lrelu(a.y + ad.y) - m1) : (lrelu(a.x + ad.x) - m0);
        float alpha = __expf(e) * (head ? inv1 : inv0);
        uint2 r = H2[srcj * 32 + lane];
        float2 p = __half22float2(*(__half2*)&r.x);
        float2 q = __half22float2(*(__half2*)&r.y);
        acc0.x += alpha * p.x; acc0.y += alpha * p.y;
        acc0.z += alpha * q.x; acc0.w += alpha * q.y;
    }

    float4 b = ((const float4*)bias)[lane];
    acc0.x += b.x; acc0.y += b.y; acc0.z += b.z; acc0.w += b.w;
    ((float4*)g_agg)[w * 32 + lane] = acc0;

    // ---- fused BN statistics: block-reduce 8 rows, one atomic per column ----
    ((float4*)s_red[wb])[lane] = acc0;
    __syncthreads();
    int t = threadIdx.x;
    if (t < FD) {
        float sum = 0.f, sq = 0.f;
        #pragma unroll
        for (int b8 = 0; b8 < 8; b8++) {
            float v = s_red[b8][t];
            sum += v;
            sq = fmaf(v, v, sq);
        }
        atomicAdd(&g_bnsum[slot][t], sum);
        atomicAdd(&g_bnsq[slot][t],  sq);
    }
}

// ---------------- final BN+ELU -> out -----------------------------------------
__global__ void k_bnapply(const float* __restrict__ gamma,
                          const float* __restrict__ beta,
                          float* __restrict__ out) {
    int i = blockIdx.x * blockDim.x + threadIdx.x;
    if (i >= NN * 32) return;
    int c4 = (i & 31) * 4;
    float4 v  = ((const float4*)g_agg)[i];
    float4 gm = ((const float4*)gamma)[i & 31];
    float4 bt = ((const float4*)beta)[i & 31];
    float res[4];
    float vin[4] = {v.x, v.y, v.z, v.w};
    float gs[4]  = {gm.x, gm.y, gm.z, gm.w};
    float bs[4]  = {bt.x, bt.y, bt.z, bt.w};
    #pragma unroll
    for (int k = 0; k < 4; k++) {
        int c = c4 + k;
        float mean = g_bnsum[1][c] * (1.f / NN);
        float var  = g_bnsq[1][c] * (1.f / NN) - mean * mean;
        float is   = rsqrtf(var + BN_EPS);
        float y = (vin[k] - mean) * is * gs[k] + bs[k];
        res[k] = y > 0.f ? y : expm1f(y);
    }
    ((float4*)out)[i] = make_float4(res[0], res[1], res[2], res[3]);
}

// ---------------- launch: kernel launches ONLY (graph-capture safe) -----------
extern "C" void kernel_launch(void* const* d_in, const int* in_sizes, int n_in,
                              void* d_out, int out_size) {
    const float* x        = (const float*)d_in[0];
    const int*   eidx     = (const int*)d_in[1];
    const float* W1       = (const float*)d_in[2];
    const float* att_src1 = (const float*)d_in[3];
    const float* att_dst1 = (const float*)d_in[4];
    const float* b1       = (const float*)d_in[5];
    const float* W2       = (const float*)d_in[6];
    const float* att_src2 = (const float*)d_in[7];
    const float* att_dst2 = (const float*)d_in[8];
    const float* b2       = (const float*)d_in[9];
    const float* g1       = (const float*)d_in[10];
    const float* be1      = (const float*)d_in[11];
    const float* g2       = (const float*)d_in[12];
    const float* be2      = (const float*)d_in[13];
    float* out = (float*)d_out;

    const int* esrc = eidx;
    const int* edst = eidx + EE;

    const int WARP_BLOCKS = NN / 8;                 // 6250 (exact)
    const int MMA_BLOCKS  = (NN + 127) / 128;       // 391
    const int E4_BLOCKS   = (EE / 4 + 255) / 256;

    k_prep<<<(NN + 255) / 256, 256>>>(W1, W2);
    k_hist<<<E4_BLOCKS, 256>>>(edst);
    k_scan<<<1, 1024>>>();
    k_scatter<<<E4_BLOCKS, 256>>>(esrc, edst);

    // --- layer 1 (BN stats fused into agg) ---
    k_gemm_mma<<<MMA_BLOCKS, 256>>>(x, g1, be1, att_src1, att_dst1, 0);
    k_agg<<<WARP_BLOCKS, 256>>>(b1, 0);

    // --- layer 2 (BN+ELU of layer 1 fused into A-load; stats fused into agg) ---
    k_gemm_mma<<<MMA_BLOCKS, 256>>>(x, g2, be2, att_src2, att_dst2, 1);
    k_agg<<<WARP_BLOCKS, 256>>>(b2, 1);
    k_bnapply<<<WARP_BLOCKS, 256>>>(g2, be2, out);
}

// round 15
// speedup vs baseline: 1.2106x; 1.0069x over previous
#include <cuda_runtime.h>
#include <cuda_fp16.h>
#include <cstdint>

#define NN 50000
#define EE 800000
#define FD 128           // hidden = heads*C = 2*64
#define NEG 0.2f
#define BN_EPS 1e-5f

// ---------------- scratch (device globals; referenced ONLY inside kernels) ----
__device__ __align__(16) uint32_t g_h2[NN * 64];      // h in half2 (ch 2i,2i+1)
__device__ __align__(16) float    g_agg[NN * FD];     // GAT aggregate (pre-BN)
__device__ __align__(16) uint32_t g_whi[2][FD * FD];  // W tf32-hi bits per layer
__device__ __align__(16) uint32_t g_wlo[2][FD * FD];  // W tf32-lo bits per layer
__device__ float2 g_asrc[NN];
__device__ float2 g_adst[NN];
__device__ int    g_counts[NN];
__device__ int    g_cursor[NN];
__device__ int    g_offsets[NN + 1];
__device__ int    g_srt[EE];
__device__ float  g_bnsum[2][FD];
__device__ float  g_bnsq[2][FD];
__device__ unsigned int g_gmax[2][2];   // [layer][head]: encoded global max of asrc

__device__ __forceinline__ int clampN(int v) {
    return v < 0 ? 0 : (v >= NN ? NN - 1 : v);
}
__device__ __forceinline__ float lrelu(float v) { return v > 0.f ? v : NEG * v; }

// monotone float<->uint encoding for atomicMax
__device__ __forceinline__ unsigned int encf(float f) {
    unsigned int u = __float_as_uint(f);
    return (u & 0x80000000u) ? ~u : (u | 0x80000000u);
}
__device__ __forceinline__ float decf(unsigned int u) {
    return __uint_as_float((u & 0x80000000u) ? (u ^ 0x80000000u) : ~u);
}

__device__ __forceinline__ uint32_t f2tf32(float f) {
    uint32_t r;
    asm("cvt.rna.tf32.f32 %0, %1;" : "=r"(r) : "f"(f));
    return r;
}

#define MMA_TF32(d, a, b0, b1) \
    asm volatile("mma.sync.aligned.m16n8k8.row.col.f32.tf32.tf32.f32 " \
        "{%0,%1,%2,%3}, {%4,%5,%6,%7}, {%8,%9}, {%0,%1,%2,%3};" \
        : "+f"((d)[0]), "+f"((d)[1]), "+f"((d)[2]), "+f"((d)[3]) \
        : "r"((a)[0]), "r"((a)[1]), "r"((a)[2]), "r"((a)[3]), \
          "r"(b0), "r"(b1))

// -------- prep: zero counters/stats + precompute W tf32 hi/lo (both layers) ---
__global__ void k_prep(const float* __restrict__ W1, const float* __restrict__ W2) {
    int i = blockIdx.x * blockDim.x + threadIdx.x;
    if (i < NN) g_counts[i] = 0;
    if (i < FD) {
        g_bnsum[0][i] = 0.f; g_bnsq[0][i] = 0.f;
        g_bnsum[1][i] = 0.f; g_bnsq[1][i] = 0.f;
    }
    if (i < 4) g_gmax[i >> 1][i & 1] = 0u;
    if (i < FD * FD) {
        #pragma unroll
        for (int l = 0; l < 2; l++) {
            float w = (l ? W2 : W1)[i];
            uint32_t hb = f2tf32(w);
            float lof = w - __uint_as_float(hb);
            g_whi[l][i] = hb;
            g_wlo[l][i] = f2tf32(lof);
        }
    }
}

// ---------------- counting sort by destination --------------------------------
__global__ void k_hist(const int* __restrict__ dst) {
    int e4 = blockIdx.x * blockDim.x + threadIdx.x;
    if (e4 < EE / 4) {
        int4 d = ((const int4*)dst)[e4];
        atomicAdd(&g_counts[clampN(d.x)], 1);
        atomicAdd(&g_counts[clampN(d.y)], 1);
        atomicAdd(&g_counts[clampN(d.z)], 1);
        atomicAdd(&g_counts[clampN(d.w)], 1);
    }
}

__global__ void k_scan() {
    __shared__ int ssum[1024];
    const int CH = (NN + 1023) / 1024;
    int t = threadIdx.x;
    int base = t * CH;
    int s = 0;
    for (int i = 0; i < CH; i++) {
        int idx = base + i;
        if (idx < NN) s += g_counts[idx];
    }
    ssum[t] = s;
    __syncthreads();
    for (int o = 1; o < 1024; o <<= 1) {
        int u = (t >= o) ? ssum[t - o] : 0;
        __syncthreads();
        ssum[t] += u;
        __syncthreads();
    }
    int off = ssum[t] - s;
    for (int i = 0; i < CH; i++) {
        int idx = base + i;
        if (idx < NN) {
            g_offsets[idx] = off;
            g_cursor[idx]  = off;
            off += g_counts[idx];
        }
    }
    if (t == 0) g_offsets[NN] = EE;
}

__global__ void k_scatter(const int* __restrict__ src,
                          const int* __restrict__ dst) {
    int e4 = blockIdx.x * blockDim.x + threadIdx.x;
    if (e4 < EE / 4) {
        int4 d = ((const int4*)dst)[e4];
        int4 s = ((const int4*)src)[e4];
        int p;
        p = atomicAdd(&g_cursor[clampN(d.x)], 1); if (p >= 0 && p < EE) g_srt[p] = clampN(s.x);
        p = atomicAdd(&g_cursor[clampN(d.y)], 1); if (p >= 0 && p < EE) g_srt[p] = clampN(s.y);
        p = atomicAdd(&g_cursor[clampN(d.z)], 1); if (p >= 0 && p < EE) g_srt[p] = clampN(s.z);
        p = atomicAdd(&g_cursor[clampN(d.w)], 1); if (p >= 0 && p < EE) g_srt[p] = clampN(s.w);
    }
}

// ============== 3xTF32 mma.sync GEMM + attention-score epilogue ==============
// h stored to fp16 (half2) -> halves the aggregation gather traffic.
#define ASTR 20    // A row stride (conflict-free fragment access)
#define BSTR 136   // B k-row stride; 136 % 32 == 8 -> conflict-free
#define TF32_MASK 0xFFFFE000u

__global__ void k_gemm_mma(const float* __restrict__ X,
                           const float* __restrict__ gamma, const float* __restrict__ beta,
                           const float* __restrict__ att_s, const float* __restrict__ att_d,
                           int mode) {
    __shared__ uint32_t sAhi[128 * ASTR];
    __shared__ uint32_t sAlo[128 * ASTR];
    __shared__ uint32_t sBhi[16 * BSTR];
    __shared__ uint32_t sBlo[16 * BSTR];
    __shared__ float s_atts[FD], s_attd[FD], s_bnA[FD], s_bnB[FD];
    __shared__ unsigned int s_m0, s_m1;

    int t = threadIdx.x;
    int rb = blockIdx.x * 128;

    if (t == 0) { s_m0 = 0u; s_m1 = 0u; }
    if (t < FD) {
        s_atts[t] = att_s[t];
        s_attd[t] = att_d[t];
        if (mode) {
            float mean = g_bnsum[0][t] * (1.f / NN);
            float var  = g_bnsq[0][t] * (1.f / NN) - mean * mean;
            float a = gamma[t] * rsqrtf(var + BN_EPS);
            s_bnA[t] = a;
            s_bnB[t] = beta[t] - mean * a;
        }
    }

    int lane = t & 31, warp = t >> 5;
    int g  = lane >> 2;       // groupID (row within fragment)
    int t4 = lane & 3;        // threadID in group
    int wr = warp * 16;       // warp row base within tile

    float d[16][4];
    #pragma unroll
    for (int nt = 0; nt < 16; nt++) {
        d[nt][0] = 0.f; d[nt][1] = 0.f; d[nt][2] = 0.f; d[nt][3] = 0.f;
    }

    const float4* X4 = (const float4*)(mode ? (const float*)g_agg : X);
    const uint4* Whi4 = (const uint4*)g_whi[mode];
    const uint4* Wlo4 = (const uint4*)g_wlo[mode];

    for (int kc = 0; kc < 8; kc++) {
        __syncthreads();

        // --- stage A chunk: mask-based hi + exact residual lo ---
        #pragma unroll
        for (int j = 0; j < 2; j++) {
            int idx = t + j * 256;
            int row = idx >> 2, c4 = idx & 3;
            int grow = rb + row;
            float4 v = (grow < NN) ? X4[grow * 32 + kc * 4 + c4]
                                   : make_float4(0.f, 0.f, 0.f, 0.f);
            float vv[4] = {v.x, v.y, v.z, v.w};
            int sbase = row * ASTR + c4 * 4;
            #pragma unroll
            for (int i = 0; i < 4; i++) {
                float val = vv[i];
                if (mode) {
                    int c = kc * 16 + c4 * 4 + i;
                    float y = s_bnA[c] * val + s_bnB[c];
                    val = y > 0.f ? y : expm1f(y);
                }
                uint32_t hb = __float_as_uint(val) & TF32_MASK;
                float lof = val - __uint_as_float(hb);
                sAhi[sbase + i] = hb;
                sAlo[sbase + i] = __float_as_uint(lof) & TF32_MASK;
            }
        }

        // --- stage B chunk: pure copy of preconverted bits ---
        #pragma unroll
        for (int j = 0; j < 2; j++) {
            int idx = t + j * 256;
            int k = idx >> 5, c4 = idx & 31;
            uint4 h = Whi4[(kc * 16 + k) * 32 + c4];
            uint4 l = Wlo4[(kc * 16 + k) * 32 + c4];
            int sbase = k * BSTR + c4 * 4;
            sBhi[sbase + 0] = h.x; sBhi[sbase + 1] = h.y;
            sBhi[sbase + 2] = h.z; sBhi[sbase + 3] = h.w;
            sBlo[sbase + 0] = l.x; sBlo[sbase + 1] = l.y;
            sBlo[sbase + 2] = l.z; sBlo[sbase + 3] = l.w;
        }
        __syncthreads();

        #pragma unroll
        for (int ks = 0; ks < 2; ks++) {
            int kk = ks * 8;
            uint32_t ahi[4], alo[4];
            int ab = (wr + g) * ASTR + kk;
            ahi[0] = sAhi[ab + t4];
            ahi[1] = sAhi[ab + 8 * ASTR + t4];
            ahi[2] = sAhi[ab + t4 + 4];
            ahi[3] = sAhi[ab + 8 * ASTR + t4 + 4];
            alo[0] = sAlo[ab + t4];
            alo[1] = sAlo[ab + 8 * ASTR + t4];
            alo[2] = sAlo[ab + t4 + 4];
            alo[3] = sAlo[ab + 8 * ASTR + t4 + 4];
            #pragma unroll
            for (int nt = 0; nt < 16; nt++) {
                int bcol = nt * 8 + g;
                uint32_t bh0 = sBhi[(kk + t4) * BSTR + bcol];
                uint32_t bh1 = sBhi[(kk + t4 + 4) * BSTR + bcol];
                uint32_t bl0 = sBlo[(kk + t4) * BSTR + bcol];
                uint32_t bl1 = sBlo[(kk + t4 + 4) * BSTR + bcol];
                MMA_TF32(d[nt], ahi, bh0, bh1);
                MMA_TF32(d[nt], ahi, bl0, bl1);
                MMA_TF32(d[nt], alo, bh0, bh1);
            }
        }
    }

    // --- epilogue: store h (fp16), attention dots, block max of asrc ---
    int r0 = rb + wr + g;
    int r1 = r0 + 8;
    float ds0h0 = 0.f, ds0h1 = 0.f, dd0h0 = 0.f, dd0h1 = 0.f;
    float ds1h0 = 0.f, ds1h1 = 0.f, dd1h0 = 0.f, dd1h1 = 0.f;
    #pragma unroll
    for (int nt = 0; nt < 16; nt++) {
        int c0 = nt * 8 + t4 * 2;
        float a0 = s_atts[c0], a1 = s_atts[c0 + 1];
        float b0 = s_attd[c0], b1 = s_attd[c0 + 1];
        float p0 = d[nt][0] * a0 + d[nt][1] * a1;
        float q0 = d[nt][0] * b0 + d[nt][1] * b1;
        float p1 = d[nt][2] * a0 + d[nt][3] * a1;
        float q1 = d[nt][2] * b0 + d[nt][3] * b1;
        if (nt < 8) { ds0h0 += p0; dd0h0 += q0; ds1h0 += p1; dd1h0 += q1; }
        else        { ds0h1 += p0; dd0h1 += q0; ds1h1 += p1; dd1h1 += q1; }
        if (r0 < NN) {
            __half2 ph = __floats2half2_rn(d[nt][0], d[nt][1]);
            g_h2[r0 * 64 + (c0 >> 1)] = *(uint32_t*)&ph;
        }
        if (r1 < NN) {
            __half2 ph = __floats2half2_rn(d[nt][2], d[nt][3]);
            g_h2[r1 * 64 + (c0 >> 1)] = *(uint32_t*)&ph;
        }
    }
    #pragma unroll
    for (int o = 1; o <= 2; o <<= 1) {
        ds0h0 += __shfl_xor_sync(0xFFFFFFFFu, ds0h0, o);
        ds0h1 += __shfl_xor_sync(0xFFFFFFFFu, ds0h1, o);
        dd0h0 += __shfl_xor_sync(0xFFFFFFFFu, dd0h0, o);
        dd0h1 += __shfl_xor_sync(0xFFFFFFFFu, dd0h1, o);
        ds1h0 += __shfl_xor_sync(0xFFFFFFFFu, ds1h0, o);
        ds1h1 += __shfl_xor_sync(0xFFFFFFFFu, ds1h1, o);
        dd1h0 += __shfl_xor_sync(0xFFFFFFFFu, dd1h0, o);
        dd1h1 += __shfl_xor_sync(0xFFFFFFFFu, dd1h1, o);
    }
    if (t4 == 0) {
        if (r0 < NN) {
            g_asrc[r0] = make_float2(ds0h0, ds0h1);
            g_adst[r0] = make_float2(dd0h0, dd0h1);
            atomicMax(&s_m0, encf(ds0h0));
            atomicMax(&s_m1, encf(ds0h1));
        }
        if (r1 < NN) {
            g_asrc[r1] = make_float2(ds1h0, ds1h1);
            g_adst[r1] = make_float2(dd1h0, dd1h1);
            atomicMax(&s_m0, encf(ds1h0));
            atomicMax(&s_m1, encf(ds1h1));
        }
    }
    __syncthreads();
    if (t == 0) {
        atomicMax(&g_gmax[mode][0], s_m0);
        atomicMax(&g_gmax[mode][1], s_m1);
    }
}

// ----- warp-per-dst aggregation (fp16 h gather) + fused BN statistics --------
// grid is exactly NN/8 blocks x 8 warps: every warp owns one valid node.
__global__ void k_agg(const float* __restrict__ bias, int slot) {
    __shared__ int   s_src[8][64];
    __shared__ float s_a0[8][64];
    __shared__ float s_a1[8][64];
    __shared__ float s_red[8][128];
    int wb   = threadIdx.x >> 5;
    int lane = threadIdx.x & 31;
    int w = (blockIdx.x * blockDim.x + threadIdx.x) >> 5;
    int start = g_offsets[w];
    int deg   = g_offsets[w + 1] - start;

    float2 ad    = g_adst[w];
    float2 aself = g_asrc[w];
    float m0 = lrelu(decf(g_gmax[slot][0]) + ad.x);
    float m1 = lrelu(decf(g_gmax[slot][1]) + ad.y);

    // single pass: gather asrc, exp, stage (first 64 edges), accumulate sums
    float s0 = 0.f, s1 = 0.f;
    #pragma unroll
    for (int it = 0; it < 2; it++) {
        int j = it * 32 + lane;
        bool have = j < deg;
        int sj = 0;
        float x0 = 0.f, x1 = 0.f;
        if (have) {
            sj = g_srt[start + j];
            float2 a = g_asrc[sj];
            x0 = __expf(lrelu(a.x + ad.x) - m0);
            x1 = __expf(lrelu(a.y + ad.y) - m1);
        }
        s_src[wb][it * 32 + lane] = sj;
        s_a0[wb][it * 32 + lane] = x0;
        s_a1[wb][it * 32 + lane] = x1;
        s0 += x0; s1 += x1;
    }
    for (int j = 64 + lane; j < deg; j += 32) {   // astronomically rare tail
        float2 a = g_asrc[g_srt[start + j]];
        s0 += __expf(lrelu(a.x + ad.x) - m0);
        s1 += __expf(lrelu(a.y + ad.y) - m1);
    }
    #pragma unroll
    for (int o = 16; o; o >>= 1) {
        s0 += __shfl_xor_sync(0xFFFFFFFFu, s0, o);
        s1 += __shfl_xor_sync(0xFFFFFFFFu, s1, o);
    }
    float xs0 = __expf(lrelu(aself.x + ad.x) - m0);
    float xs1 = __expf(lrelu(aself.y + ad.y) - m1);
    s0 += xs0; s1 += xs1;
    float inv0 = 1.f / (s0 + 1e-16f);
    float inv1 = 1.f / (s1 + 1e-16f);

    // normalize own staged entries (lane-local), then make visible
    s_a0[wb][lane]      *= inv0;
    s_a0[wb][lane + 32] *= inv0;
    s_a1[wb][lane]      *= inv1;
    s_a1[wb][lane + 32] *= inv1;
    __syncwarp();

    int head = lane >> 4;
    const uint2* H2 = (const uint2*)g_h2;   // H2[row*32+lane] = ch 4l..4l+3

    float salpha = head ? xs1 * inv1 : xs0 * inv0;
    uint2 raw = H2[w * 32 + lane];
    float2 f01 = __half22float2(*(__half2*)&raw.x);
    float2 f23 = __half22float2(*(__half2*)&raw.y);
    float4 acc0 = make_float4(salpha * f01.x, salpha * f01.y,
                              salpha * f23.x, salpha * f23.y);
    float4 acc1 = make_float4(0.f, 0.f, 0.f, 0.f);
    float4 acc2 = make_float4(0.f, 0.f, 0.f, 0.f);
    float4 acc3 = make_float4(0.f, 0.f, 0.f, 0.f);

    const float* sal = head ? s_a1[wb] : s_a0[wb];
    int nd = deg < 64 ? deg : 64;
    int j = 0;
    for (; j + 3 < nd; j += 4) {     // quad accumulators -> 4x load MLP
        int i0 = s_src[wb][j],     i1 = s_src[wb][j + 1];
        int i2 = s_src[wb][j + 2], i3 = s_src[wb][j + 3];
        float a0 = sal[j],     a1 = sal[j + 1];
        float a2 = sal[j + 2], a3 = sal[j + 3];
        uint2 r0 = H2[i0 * 32 + lane];
        uint2 r1 = H2[i1 * 32 + lane];
        uint2 r2 = H2[i2 * 32 + lane];
        uint2 r3 = H2[i3 * 32 + lane];
        float2 p, q;
        p = __half22float2(*(__half2*)&r0.x); q = __half22float2(*(__half2*)&r0.y);
        acc0.x += a0 * p.x; acc0.y += a0 * p.y; acc0.z += a0 * q.x; acc0.w += a0 * q.y;
        p = __half22float2(*(__half2*)&r1.x); q = __half22float2(*(__half2*)&r1.y);
        acc1.x += a1 * p.x; acc1.y += a1 * p.y; acc1.z += a1 * q.x; acc1.w += a1 * q.y;
        p = __half22float2(*(__half2*)&r2.x); q = __half22float2(*(__half2*)&r2.y);
        acc2.x += a2 * p.x; acc2.y += a2 * p.y; acc2.z += a2 * q.x; acc2.w += a2 * q.y;
        p = __half22float2(*(__half2*)&r3.x); q = __half22float2(*(__half2*)&r3.y);
        acc3.x += a3 * p.x; acc3.y += a3 * p.y; acc3.z += a3 * q.x; acc3.w += a3 * q.y;
    }
    for (; j < nd; j++) {
        int sa = s_src[wb][j];
        float aa = sal[j];
        uint2 r = H2[sa * 32 + lane];
        float2 p = __half22float2(*(__half2*)&r.x);
        float2 q = __half22float2(*(__half2*)&r.y);
        acc0.x += aa * p.x; acc0.y += aa * p.y; acc0.z += aa * q.x; acc0.w += aa * q.y;
    }
    acc0.x += acc1.x + acc2.x + acc3.x;
    acc0.y += acc1.y + acc2.y + acc3.y;
    acc0.z += acc1.z + acc2.z + acc3.z;
    acc0.w += acc1.w + acc2.w + acc3.w;

    for (int jj = 64; jj < deg; jj++) {   // rare tail: recompute alpha inline
        int srcj = g_srt[start + jj];
        float2 a = g_asrc[srcj];
        float e = head ? (lrelu(a.y + ad.y) - m1) : (lrelu(a.x + ad.x) - m0);
        float alpha = __expf(e) * (head ? inv1 : inv0);
        uint2 r = H2[srcj * 32 + lane];
        float2 p = __half22float2(*(__half2*)&r.x);
        float2 q = __half22float2(*(__half2*)&r.y);
        acc0.x += alpha * p.x; acc0.y += alpha * p.y;
        acc0.z += alpha * q.x; acc0.w += alpha * q.y;
    }

    float4 b = ((const float4*)bias)[lane];
    acc0.x += b.x; acc0.y += b.y; acc0.z += b.z; acc0.w += b.w;
    ((float4*)g_agg)[w * 32 + lane] = acc0;

    // ---- fused BN statistics: block-reduce 8 rows, one atomic per column ----
    ((float4*)s_red[wb])[lane] = acc0;
    __syncthreads();
    int t = threadIdx.x;
    if (t < FD) {
        float sum = 0.f, sq = 0.f;
        #pragma unroll
        for (int b8 = 0; b8 < 8; b8++) {
            float v = s_red[b8][t];
            sum += v;
            sq = fmaf(v, v, sq);
        }
        atomicAdd(&g_bnsum[slot][t], sum);
        atomicAdd(&g_bnsq[slot][t],  sq);
    }
}

// ---------------- final BN+ELU -> out -----------------------------------------
__global__ void k_bnapply(const float* __restrict__ gamma,
                          const float* __restrict__ beta,
                          float* __restrict__ out) {
    int i = blockIdx.x * blockDim.x + threadIdx.x;
    if (i >= NN * 32) return;
    int c4 = (i & 31) * 4;
    float4 v  = ((const float4*)g_agg)[i];
    float4 gm = ((const float4*)gamma)[i & 31];
    float4 bt = ((const float4*)beta)[i & 31];
    float res[4];
    float vin[4] = {v.x, v.y, v.z, v.w};
    float gs[4]  = {gm.x, gm.y, gm.z, gm.w};
    float bs[4]  = {bt.x, bt.y, bt.z, bt.w};
    #pragma unroll
    for (int k = 0; k < 4; k++) {
        int c = c4 + k;
        float mean = g_bnsum[1][c] * (1.f / NN);
        float var  = g_bnsq[1][c] * (1.f / NN) - mean * mean;
        float is   = rsqrtf(var + BN_EPS);
        float y = (vin[k] - mean) * is * gs[k] + bs[k];
        res[k] = y > 0.f ? y : expm1f(y);
    }
    ((float4*)out)[i] = make_float4(res[0], res[1], res[2], res[3]);
}

// ---------------- launch: fork/join capture graph -----------------------------
// kernel_launch is called only for the correctness run and the single graph
// capture, so per-call stream/event creation (never destroyed) leaks a handful
// of host-side handles total, keeps work deterministic, and keeps the captured
// graph structure identical on every call.
extern "C" void kernel_launch(void* const* d_in, const int* in_sizes, int n_in,
                              void* d_out, int out_size) {
    const float* x        = (const float*)d_in[0];
    const int*   eidx     = (const int*)d_in[1];
    const float* W1       = (const float*)d_in[2];
    const float* att_src1 = (const float*)d_in[3];
    const float* att_dst1 = (const float*)d_in[4];
    const float* b1       = (const float*)d_in[5];
    const float* W2       = (const float*)d_in[6];
    const float* att_src2 = (const float*)d_in[7];
    const float* att_dst2 = (const float*)d_in[8];
    const float* b2       = (const float*)d_in[9];
    const float* g1       = (const float*)d_in[10];
    const float* be1      = (const float*)d_in[11];
    const float* g2       = (const float*)d_in[12];
    const float* be2      = (const float*)d_in[13];
    float* out = (float*)d_out;

    const int* esrc = eidx;
    const int* edst = eidx + EE;

    const int WARP_BLOCKS = NN / 8;                 // 6250 (exact)
    const int MMA_BLOCKS  = (NN + 127) / 128;       // 391
    const int E4_BLOCKS   = (EE / 4 + 255) / 256;

    cudaStream_t side;
    cudaEvent_t ev_fork, ev_join;
    cudaStreamCreateWithFlags(&side, cudaStreamNonBlocking);
    cudaEventCreateWithFlags(&ev_fork, cudaEventDisableTiming);
    cudaEventCreateWithFlags(&ev_join, cudaEventDisableTiming);

    // prep (zeros counts + converts W) on main stream
    k_prep<<<(NN + 255) / 256, 256>>>(W1, W2);

    // fork: CSR build on side stream, concurrent with layer-1 GEMM on main
    cudaEventRecord(ev_fork, 0);
    cudaStreamWaitEvent(side, ev_fork, 0);
    k_hist<<<E4_BLOCKS, 256, 0, side>>>(edst);
    k_scan<<<1, 1024, 0, side>>>();
    k_scatter<<<E4_BLOCKS, 256, 0, side>>>(esrc, edst);
    cudaEventRecord(ev_join, side);

    k_gemm_mma<<<MMA_BLOCKS, 256>>>(x, g1, be1, att_src1, att_dst1, 0);

    // join: aggregation needs both GEMM output and the CSR
    cudaStreamWaitEvent(0, ev_join, 0);
    k_agg<<<WARP_BLOCKS, 256>>>(b1, 0);

    // --- layer 2 (BN+ELU of layer 1 fused into A-load; stats fused into agg) ---
    k_gemm_mma<<<MMA_BLOCKS, 256>>>(x, g2, be2, att_src2, att_dst2, 1);
    k_agg<<<WARP_BLOCKS, 256>>>(b2, 1);
    k_bnapply<<<WARP_BLOCKS, 256>>>(g2, be2, out);
}

// round 16
// speedup vs baseline: 1.2109x; 1.0002x over previous
#include <cuda_runtime.h>
#include <cuda_fp16.h>
#include <cstdint>

#define NN 50000
#define EE 800000
#define FD 128           // hidden = heads*C = 2*64
#define NEG 0.2f
#define BN_EPS 1e-5f

// ---------------- scratch (device globals; referenced ONLY inside kernels) ----
__device__ __align__(16) uint32_t g_h2[NN * 64];      // h in half2 (ch 2i,2i+1)
__device__ __align__(16) float    g_agg[NN * FD];     // GAT aggregate (pre-BN)
__device__ __align__(16) uint32_t g_whi[2][FD * FD];  // W tf32-hi bits per layer
__device__ __align__(16) uint32_t g_wlo[2][FD * FD];  // W tf32-lo bits per layer
__device__ float2 g_asrc[NN];
__device__ float2 g_adst[NN];
__device__ int    g_counts[NN];
__device__ int    g_cursor[NN];
__device__ int    g_offsets[NN + 1];
__device__ int    g_srt[EE];
__device__ float  g_bnsum[2][FD];
__device__ float  g_bnsq[2][FD];
__device__ unsigned int g_gmax[2][2];   // [layer][head]: encoded global max of asrc

__device__ __forceinline__ int clampN(int v) {
    return v < 0 ? 0 : (v >= NN ? NN - 1 : v);
}
__device__ __forceinline__ float lrelu(float v) { return v > 0.f ? v : NEG * v; }

// monotone float<->uint encoding for atomicMax
__device__ __forceinline__ unsigned int encf(float f) {
    unsigned int u = __float_as_uint(f);
    return (u & 0x80000000u) ? ~u : (u | 0x80000000u);
}
__device__ __forceinline__ float decf(unsigned int u) {
    return __uint_as_float((u & 0x80000000u) ? (u ^ 0x80000000u) : ~u);
}

__device__ __forceinline__ uint32_t f2tf32(float f) {
    uint32_t r;
    asm("cvt.rna.tf32.f32 %0, %1;" : "=r"(r) : "f"(f));
    return r;
}

#define MMA_TF32(d, a, b0, b1) \
    asm volatile("mma.sync.aligned.m16n8k8.row.col.f32.tf32.tf32.f32 " \
        "{%0,%1,%2,%3}, {%4,%5,%6,%7}, {%8,%9}, {%0,%1,%2,%3};" \
        : "+f"((d)[0]), "+f"((d)[1]), "+f"((d)[2]), "+f"((d)[3]) \
        : "r"((a)[0]), "r"((a)[1]), "r"((a)[2]), "r"((a)[3]), \
          "r"(b0), "r"(b1))

// -------- prep: zero counters/stats + precompute W tf32 hi/lo (both layers) ---
__global__ void k_prep(const float* __restrict__ W1, const float* __restrict__ W2) {
    int i = blockIdx.x * blockDim.x + threadIdx.x;
    if (i < NN) g_counts[i] = 0;
    if (i < FD) {
        g_bnsum[0][i] = 0.f; g_bnsq[0][i] = 0.f;
        g_bnsum[1][i] = 0.f; g_bnsq[1][i] = 0.f;
    }
    if (i < 4) g_gmax[i >> 1][i & 1] = 0u;
    if (i < FD * FD) {
        #pragma unroll
        for (int l = 0; l < 2; l++) {
            float w = (l ? W2 : W1)[i];
            uint32_t hb = f2tf32(w);
            float lof = w - __uint_as_float(hb);
            g_whi[l][i] = hb;
            g_wlo[l][i] = f2tf32(lof);
        }
    }
}

// ---------------- counting sort by destination --------------------------------
__global__ void k_hist(const int* __restrict__ dst) {
    int e4 = blockIdx.x * blockDim.x + threadIdx.x;
    if (e4 < EE / 4) {
        int4 d = ((const int4*)dst)[e4];
        atomicAdd(&g_counts[clampN(d.x)], 1);
        atomicAdd(&g_counts[clampN(d.y)], 1);
        atomicAdd(&g_counts[clampN(d.z)], 1);
        atomicAdd(&g_counts[clampN(d.w)], 1);
    }
}

__global__ void k_scan() {
    __shared__ int ssum[1024];
    const int CH = (NN + 1023) / 1024;
    int t = threadIdx.x;
    int base = t * CH;
    int s = 0;
    for (int i = 0; i < CH; i++) {
        int idx = base + i;
        if (idx < NN) s += g_counts[idx];
    }
    ssum[t] = s;
    __syncthreads();
    for (int o = 1; o < 1024; o <<= 1) {
        int u = (t >= o) ? ssum[t - o] : 0;
        __syncthreads();
        ssum[t] += u;
        __syncthreads();
    }
    int off = ssum[t] - s;
    for (int i = 0; i < CH; i++) {
        int idx = base + i;
        if (idx < NN) {
            g_offsets[idx] = off;
            g_cursor[idx]  = off;
            off += g_counts[idx];
        }
    }
    if (t == 0) g_offsets[NN] = EE;
}

__global__ void k_scatter(const int* __restrict__ src,
                          const int* __restrict__ dst) {
    int e4 = blockIdx.x * blockDim.x + threadIdx.x;
    if (e4 < EE / 4) {
        int4 d = ((const int4*)dst)[e4];
        int4 s = ((const int4*)src)[e4];
        int p;
        p = atomicAdd(&g_cursor[clampN(d.x)], 1); if (p >= 0 && p < EE) g_srt[p] = clampN(s.x);
        p = atomicAdd(&g_cursor[clampN(d.y)], 1); if (p >= 0 && p < EE) g_srt[p] = clampN(s.y);
        p = atomicAdd(&g_cursor[clampN(d.z)], 1); if (p >= 0 && p < EE) g_srt[p] = clampN(s.z);
        p = atomicAdd(&g_cursor[clampN(d.w)], 1); if (p >= 0 && p < EE) g_srt[p] = clampN(s.w);
    }
}

// ============== 3xTF32 mma.sync GEMM + attention-score epilogue ==============
// h stored to fp16 (half2) -> halves the aggregation gather traffic.
#define ASTR 20    // A row stride (conflict-free fragment access)
#define BSTR 136   // B k-row stride; 136 % 32 == 8 -> conflict-free
#define TF32_MASK 0xFFFFE000u

__global__ void k_gemm_mma(const float* __restrict__ X,
                           const float* __restrict__ gamma, const float* __restrict__ beta,
                           const float* __restrict__ att_s, const float* __restrict__ att_d,
                           int mode) {
    __shared__ uint32_t sAhi[128 * ASTR];
    __shared__ uint32_t sAlo[128 * ASTR];
    __shared__ uint32_t sBhi[16 * BSTR];
    __shared__ uint32_t sBlo[16 * BSTR];
    __shared__ float s_atts[FD], s_attd[FD], s_bnA[FD], s_bnB[FD];
    __shared__ unsigned int s_m0, s_m1;

    int t = threadIdx.x;
    int rb = blockIdx.x * 128;

    if (t == 0) { s_m0 = 0u; s_m1 = 0u; }
    if (t < FD) {
        s_atts[t] = att_s[t];
        s_attd[t] = att_d[t];
        if (mode) {
            float mean = g_bnsum[0][t] * (1.f / NN);
            float var  = g_bnsq[0][t] * (1.f / NN) - mean * mean;
            float a = gamma[t] * rsqrtf(var + BN_EPS);
            s_bnA[t] = a;
            s_bnB[t] = beta[t] - mean * a;
        }
    }

    int lane = t & 31, warp = t >> 5;
    int g  = lane >> 2;       // groupID (row within fragment)
    int t4 = lane & 3;        // threadID in group
    int wr = warp * 16;       // warp row base within tile

    float d[16][4];
    #pragma unroll
    for (int nt = 0; nt < 16; nt++) {
        d[nt][0] = 0.f; d[nt][1] = 0.f; d[nt][2] = 0.f; d[nt][3] = 0.f;
    }

    const float4* X4 = (const float4*)(mode ? (const float*)g_agg : X);
    const uint4* Whi4 = (const uint4*)g_whi[mode];
    const uint4* Wlo4 = (const uint4*)g_wlo[mode];

    for (int kc = 0; kc < 8; kc++) {
        __syncthreads();

        // --- stage A chunk: mask-based hi + exact residual lo ---
        #pragma unroll
        for (int j = 0; j < 2; j++) {
            int idx = t + j * 256;
            int row = idx >> 2, c4 = idx & 3;
            int grow = rb + row;
            float4 v = (grow < NN) ? X4[grow * 32 + kc * 4 + c4]
                                   : make_float4(0.f, 0.f, 0.f, 0.f);
            float vv[4] = {v.x, v.y, v.z, v.w};
            int sbase = row * ASTR + c4 * 4;
            #pragma unroll
            for (int i = 0; i < 4; i++) {
                float val = vv[i];
                if (mode) {
                    int c = kc * 16 + c4 * 4 + i;
                    float y = s_bnA[c] * val + s_bnB[c];
                    val = y > 0.f ? y : expm1f(y);
                }
                uint32_t hb = __float_as_uint(val) & TF32_MASK;
                float lof = val - __uint_as_float(hb);
                sAhi[sbase + i] = hb;
                sAlo[sbase + i] = __float_as_uint(lof) & TF32_MASK;
            }
        }

        // --- stage B chunk: pure copy of preconverted bits ---
        #pragma unroll
        for (int j = 0; j < 2; j++) {
            int idx = t + j * 256;
            int k = idx >> 5, c4 = idx & 31;
            uint4 h = Whi4[(kc * 16 + k) * 32 + c4];
            uint4 l = Wlo4[(kc * 16 + k) * 32 + c4];
            int sbase = k * BSTR + c4 * 4;
            sBhi[sbase + 0] = h.x; sBhi[sbase + 1] = h.y;
            sBhi[sbase + 2] = h.z; sBhi[sbase + 3] = h.w;
            sBlo[sbase + 0] = l.x; sBlo[sbase + 1] = l.y;
            sBlo[sbase + 2] = l.z; sBlo[sbase + 3] = l.w;
        }
        __syncthreads();

        #pragma unroll
        for (int ks = 0; ks < 2; ks++) {
            int kk = ks * 8;
            uint32_t ahi[4], alo[4];
            int ab = (wr + g) * ASTR + kk;
            ahi[0] = sAhi[ab + t4];
            ahi[1] = sAhi[ab + 8 * ASTR + t4];
            ahi[2] = sAhi[ab + t4 + 4];
            ahi[3] = sAhi[ab + 8 * ASTR + t4 + 4];
            alo[0] = sAlo[ab + t4];
            alo[1] = sAlo[ab + 8 * ASTR + t4];
            alo[2] = sAlo[ab + t4 + 4];
            alo[3] = sAlo[ab + 8 * ASTR + t4 + 4];
            #pragma unroll
            for (int nt = 0; nt < 16; nt++) {
                int bcol = nt * 8 + g;
                uint32_t bh0 = sBhi[(kk + t4) * BSTR + bcol];
                uint32_t bh1 = sBhi[(kk + t4 + 4) * BSTR + bcol];
                uint32_t bl0 = sBlo[(kk + t4) * BSTR + bcol];
                uint32_t bl1 = sBlo[(kk + t4 + 4) * BSTR + bcol];
                MMA_TF32(d[nt], ahi, bh0, bh1);
                MMA_TF32(d[nt], ahi, bl0, bl1);
                MMA_TF32(d[nt], alo, bh0, bh1);
            }
        }
    }

    // --- epilogue: store h (fp16), attention dots, block max of asrc ---
    int r0 = rb + wr + g;
    int r1 = r0 + 8;
    float ds0h0 = 0.f, ds0h1 = 0.f, dd0h0 = 0.f, dd0h1 = 0.f;
    float ds1h0 = 0.f, ds1h1 = 0.f, dd1h0 = 0.f, dd1h1 = 0.f;
    #pragma unroll
    for (int nt = 0; nt < 16; nt++) {
        int c0 = nt * 8 + t4 * 2;
        float a0 = s_atts[c0], a1 = s_atts[c0 + 1];
        float b0 = s_attd[c0], b1 = s_attd[c0 + 1];
        float p0 = d[nt][0] * a0 + d[nt][1] * a1;
        float q0 = d[nt][0] * b0 + d[nt][1] * b1;
        float p1 = d[nt][2] * a0 + d[nt][3] * a1;
        float q1 = d[nt][2] * b0 + d[nt][3] * b1;
        if (nt < 8) { ds0h0 += p0; dd0h0 += q0; ds1h0 += p1; dd1h0 += q1; }
        else        { ds0h1 += p0; dd0h1 += q0; ds1h1 += p1; dd1h1 += q1; }
        if (r0 < NN) {
            __half2 ph = __floats2half2_rn(d[nt][0], d[nt][1]);
            g_h2[r0 * 64 + (c0 >> 1)] = *(uint32_t*)&ph;
        }
        if (r1 < NN) {
            __half2 ph = __floats2half2_rn(d[nt][2], d[nt][3]);
            g_h2[r1 * 64 + (c0 >> 1)] = *(uint32_t*)&ph;
        }
    }
    #pragma unroll
    for (int o = 1; o <= 2; o <<= 1) {
        ds0h0 += __shfl_xor_sync(0xFFFFFFFFu, ds0h0, o);
        ds0h1 += __shfl_xor_sync(0xFFFFFFFFu, ds0h1, o);
        dd0h0 += __shfl_xor_sync(0xFFFFFFFFu, dd0h0, o);
        dd0h1 += __shfl_xor_sync(0xFFFFFFFFu, dd0h1, o);
        ds1h0 += __shfl_xor_sync(0xFFFFFFFFu, ds1h0, o);
        ds1h1 += __shfl_xor_sync(0xFFFFFFFFu, ds1h1, o);
        dd1h0 += __shfl_xor_sync(0xFFFFFFFFu, dd1h0, o);
        dd1h1 += __shfl_xor_sync(0xFFFFFFFFu, dd1h1, o);
    }
    if (t4 == 0) {
        if (r0 < NN) {
            g_asrc[r0] = make_float2(ds0h0, ds0h1);
            g_adst[r0] = make_float2(dd0h0, dd0h1);
            atomicMax(&s_m0, encf(ds0h0));
            atomicMax(&s_m1, encf(ds0h1));
        }
        if (r1 < NN) {
            g_asrc[r1] = make_float2(ds1h0, ds1h1);
            g_adst[r1] = make_float2(dd1h0, dd1h1);
            atomicMax(&s_m0, encf(ds1h0));
            atomicMax(&s_m1, encf(ds1h1));
        }
    }
    __syncthreads();
    if (t == 0) {
        atomicMax(&g_gmax[mode][0], s_m0);
        atomicMax(&g_gmax[mode][1], s_m1);
    }
}

// ----- warp-per-dst aggregation (fp16 h gather) + fused BN statistics --------
// grid is exactly NN/8 blocks x 8 warps: every warp owns one valid node.
__global__ void k_agg(const float* __restrict__ bias, int slot) {
    __shared__ int   s_src[8][64];
    __shared__ float s_a0[8][64];
    __shared__ float s_a1[8][64];
    __shared__ float s_red[8][128];
    int wb   = threadIdx.x >> 5;
    int lane = threadIdx.x & 31;
    int w = (blockIdx.x * blockDim.x + threadIdx.x) >> 5;
    int start = g_offsets[w];
    int deg   = g_offsets[w + 1] - start;

    float2 ad    = g_adst[w];
    float2 aself = g_asrc[w];
    float m0 = lrelu(decf(g_gmax[slot][0]) + ad.x);
    float m1 = lrelu(decf(g_gmax[slot][1]) + ad.y);

    // single pass: gather asrc, exp, stage (first 64 edges), accumulate sums
    float s0 = 0.f, s1 = 0.f;
    #pragma unroll
    for (int it = 0; it < 2; it++) {
        int j = it * 32 + lane;
        bool have = j < deg;
        int sj = 0;
        float x0 = 0.f, x1 = 0.f;
        if (have) {
            sj = g_srt[start + j];
            float2 a = g_asrc[sj];
            x0 = __expf(lrelu(a.x + ad.x) - m0);
            x1 = __expf(lrelu(a.y + ad.y) - m1);
        }
        s_src[wb][it * 32 + lane] = sj;
        s_a0[wb][it * 32 + lane] = x0;
        s_a1[wb][it * 32 + lane] = x1;
        s0 += x0; s1 += x1;
    }
    for (int j = 64 + lane; j < deg; j += 32) {   // astronomically rare tail
        float2 a = g_asrc[g_srt[start + j]];
        s0 += __expf(lrelu(a.x + ad.x) - m0);
        s1 += __expf(lrelu(a.y + ad.y) - m1);
    }
    #pragma unroll
    for (int o = 16; o; o >>= 1) {
        s0 += __shfl_xor_sync(0xFFFFFFFFu, s0, o);
        s1 += __shfl_xor_sync(0xFFFFFFFFu, s1, o);
    }
    float xs0 = __expf(lrelu(aself.x + ad.x) - m0);
    float xs1 = __expf(lrelu(aself.y + ad.y) - m1);
    s0 += xs0; s1 += xs1;
    float inv0 = 1.f / (s0 + 1e-16f);
    float inv1 = 1.f / (s1 + 1e-16f);

    // normalize own staged entries (lane-local), then make visible
    s_a0[wb][lane]      *= inv0;
    s_a0[wb][lane + 32] *= inv0;
    s_a1[wb][lane]      *= inv1;
    s_a1[wb][lane + 32] *= inv1;
    __syncwarp();

    int head = lane >> 4;
    const uint2* H2 = (const uint2*)g_h2;   // H2[row*32+lane] = ch 4l..4l+3

    float salpha = head ? xs1 * inv1 : xs0 * inv0;
    uint2 raw = H2[w * 32 + lane];
    float2 f01 = __half22float2(*(__half2*)&raw.x);
    float2 f23 = __half22float2(*(__half2*)&raw.y);
    float4 acc0 = make_float4(salpha * f01.x, salpha * f01.y,
                              salpha * f23.x, salpha * f23.y);
    float4 acc1 = make_float4(0.f, 0.f, 0.f, 0.f);
    float4 acc2 = make_float4(0.f, 0.f, 0.f, 0.f);
    float4 acc3 = make_float4(0.f, 0.f, 0.f, 0.f);

    const float* sal = head ? s_a1[wb] : s_a0[wb];
    int nd = deg < 64 ? deg : 64;
    int j = 0;
    for (; j + 3 < nd; j += 4) {     // quad accumulators -> 4x load MLP
        int i0 = s_src[wb][j],     i1 = s_src[wb][j + 1];
        int i2 = s_src[wb][j + 2], i3 = s_src[wb][j + 3];
        float a0 = sal[j],     a1 = sal[j + 1];
        float a2 = sal[j + 2], a3 = sal[j + 3];
        uint2 r0 = H2[i0 * 32 + lane];
        uint2 r1 = H2[i1 * 32 + lane];
        uint2 r2 = H2[i2 * 32 + lane];
        uint2 r3 = H2[i3 * 32 + lane];
        float2 p, q;
        p = __half22float2(*(__half2*)&r0.x); q = __half22float2(*(__half2*)&r0.y);
        acc0.x += a0 * p.x; acc0.y += a0 * p.y; acc0.z += a0 * q.x; acc0.w += a0 * q.y;
        p = __half22float2(*(__half2*)&r1.x); q = __half22float2(*(__half2*)&r1.y);
        acc1.x += a1 * p.x; acc1.y += a1 * p.y; acc1.z += a1 * q.x; acc1.w += a1 * q.y;
        p = __half22float2(*(__half2*)&r2.x); q = __half22float2(*(__half2*)&r2.y);
        acc2.x += a2 * p.x; acc2.y += a2 * p.y; acc2.z += a2 * q.x; acc2.w += a2 * q.y;
        p = __half22float2(*(__half2*)&r3.x); q = __half22float2(*(__half2*)&r3.y);
        acc3.x += a3 * p.x; acc3.y += a3 * p.y; acc3.z += a3 * q.x; acc3.w += a3 * q.y;
    }
    for (; j < nd; j++) {
        int sa = s_src[wb][j];
        float aa = sal[j];
        uint2 r = H2[sa * 32 + lane];
        float2 p = __half22float2(*(__half2*)&r.x);
        float2 q = __half22float2(*(__half2*)&r.y);
        acc0.x += aa * p.x; acc0.y += aa * p.y; acc0.z += aa * q.x; acc0.w += aa * q.y;
    }
    acc0.x += acc1.x + acc2.x + acc3.x;
    acc0.y += acc1.y + acc2.y + acc3.y;
    acc0.z += acc1.z + acc2.z + acc3.z;
    acc0.w += acc1.w + acc2.w + acc3.w;

    for (int jj = 64; jj < deg; jj++) {   // rare tail: recompute alpha inline
        int srcj = g_srt[start + jj];
        float2 a = g_asrc[srcj];
        float e = head ? (lrelu(a.y + ad.y) - m1) : (lrelu(a.x + ad.x) - m0);
        float alpha = __expf(e) * (head ? inv1 : inv0);
        uint2 r = H2[srcj * 32 + lane];
        float2 p = __half22float2(*(__half2*)&r.x);
        float2 q = __half22float2(*(__half2*)&r.y);
        acc0.x += alpha * p.x; acc0.y += alpha * p.y;
        acc0.z += alpha * q.x; acc0.w += alpha * q.y;
    }

    float4 b = ((const float4*)bias)[lane];
    acc0.x += b.x; acc0.y += b.y; acc0.z += b.z; acc0.w += b.w;
    ((float4*)g_agg)[w * 32 + lane] = acc0;

    // ---- fused BN statistics: block-reduce 8 rows, one atomic per column ----
    ((float4*)s_red[wb])[lane] = acc0;
    __syncthreads();
    int t = threadIdx.x;
    if (t < FD) {
        float sum = 0.f, sq = 0.f;
        #pragma unroll
        for (int b8 = 0; b8 < 8; b8++) {
            float v = s_red[b8][t];
            sum += v;
            sq = fmaf(v, v, sq);
        }
        atomicAdd(&g_bnsum[slot][t], sum);
        atomicAdd(&g_bnsq[slot][t],  sq);
    }
}

// ---------------- final BN+ELU -> out -----------------------------------------
__global__ void k_bnapply(const float* __restrict__ gamma,
                          const float* __restrict__ beta,
                          float* __restrict__ out) {
    int i = blockIdx.x * blockDim.x + threadIdx.x;
    if (i >= NN * 32) return;
    int c4 = (i & 31) * 4;
    float4 v  = ((const float4*)g_agg)[i];
    float4 gm = ((const float4*)gamma)[i & 31];
    float4 bt = ((const float4*)beta)[i & 31];
    float res[4];
    float vin[4] = {v.x, v.y, v.z, v.w};
    float gs[4]  = {gm.x, gm.y, gm.z, gm.w};
    float bs[4]  = {bt.x, bt.y, bt.z, bt.w};
    #pragma unroll
    for (int k = 0; k < 4; k++) {
        int c = c4 + k;
        float mean = g_bnsum[1][c] * (1.f / NN);
        float var  = g_bnsq[1][c] * (1.f / NN) - mean * mean;
        float is   = rsqrtf(var + BN_EPS);
        float y = (vin[k] - mean) * is * gs[k] + bs[k];
        res[k] = y > 0.f ? y : expm1f(y);
    }
    ((float4*)out)[i] = make_float4(res[0], res[1], res[2], res[3]);
}

// ---------------- launch: fork/join capture graph -----------------------------
// kernel_launch is called only for the correctness run and the single graph
// capture, so per-call stream/event creation (never destroyed) leaks a handful
// of host-side handles total, keeps work deterministic, and keeps the captured
// graph structure identical on every call.
extern "C" void kernel_launch(void* const* d_in, const int* in_sizes, int n_in,
                              void* d_out, int out_size) {
    const float* x        = (const float*)d_in[0];
    const int*   eidx     = (const int*)d_in[1];
    const float* W1       = (const float*)d_in[2];
    const float* att_src1 = (const float*)d_in[3];
    const float* att_dst1 = (const float*)d_in[4];
    const float* b1       = (const float*)d_in[5];
    const float* W2       = (const float*)d_in[6];
    const float* att_src2 = (const float*)d_in[7];
    const float* att_dst2 = (const float*)d_in[8];
    const float* b2       = (const float*)d_in[9];
    const float* g1       = (const float*)d_in[10];
    const float* be1      = (const float*)d_in[11];
    const float* g2       = (const float*)d_in[12];
    const float* be2      = (const float*)d_in[13];
    float* out = (float*)d_out;

    const int* esrc = eidx;
    const int* edst = eidx + EE;

    const int WARP_BLOCKS = NN / 8;                 // 6250 (exact)
    const int MMA_BLOCKS  = (NN + 127) / 128;       // 391
    const int E4_BLOCKS   = (EE / 4 + 255) / 256;

    cudaStream_t side;
    cudaEvent_t ev_fork, ev_join;
    cudaStreamCreateWithFlags(&side, cudaStreamNonBlocking);
    cudaEventCreateWithFlags(&ev_fork, cudaEventDisableTiming);
    cudaEventCreateWithFlags(&ev_join, cudaEventDisableTiming);

    // prep (zeros counts + converts W) on main stream
    k_prep<<<(NN + 255) / 256, 256>>>(W1, W2);

    // fork: CSR build on side stream, concurrent with layer-1 GEMM on main
    cudaEventRecord(ev_fork, 0);
    cudaStreamWaitEvent(side, ev_fork, 0);
    k_hist<<<E4_BLOCKS, 256, 0, side>>>(edst);
    k_scan<<<1, 1024, 0, side>>>();
    k_scatter<<<E4_BLOCKS, 256, 0, side>>>(esrc, edst);
    cudaEventRecord(ev_join, side);

    k_gemm_mma<<<MMA_BLOCKS, 256>>>(x, g1, be1, att_src1, att_dst1, 0);

    // join: aggregation needs both GEMM output and the CSR
    cudaStreamWaitEvent(0, ev_join, 0);
    k_agg<<<WARP_BLOCKS, 256>>>(b1, 0);

    // --- layer 2 (BN+ELU of layer 1 fused into A-load; stats fused into agg) ---
    k_gemm_mma<<<MMA_BLOCKS, 256>>>(x, g2, be2, att_src2, att_dst2, 1);
    k_agg<<<WARP_BLOCKS, 256>>>(b2, 1);
    k_bnapply<<<WARP_BLOCKS, 256>>>(g2, be2, out);
}

// round 17
// speedup vs baseline: 1.2119x; 1.0008x over previous
#include <cuda_runtime.h>
#include <cuda_fp16.h>
#include <cstdint>

#define NN 50000
#define EE 800000
#define FD 128           // hidden = heads*C = 2*64
#define NEG 0.2f
#define BN_EPS 1e-5f

// ---------------- scratch (device globals; referenced ONLY inside kernels) ----
__device__ __align__(16) uint32_t g_h2[NN * 64];      // h in half2 (ch 2i,2i+1)
__device__ __align__(16) float    g_agg[NN * FD];     // GAT aggregate (pre-BN)
__device__ __align__(16) uint32_t g_whi[2][FD * FD];  // W tf32-hi bits per layer
__device__ __align__(16) uint32_t g_wlo[2][FD * FD];  // W tf32-lo bits per layer
__device__ float2 g_asrc[NN];
__device__ float2 g_adst[NN];
__device__ int    g_counts[NN];
__device__ int    g_cursor[NN];
__device__ int    g_offsets[NN + 1];
__device__ int    g_srt[EE];
__device__ float  g_bnsum[2][FD];
__device__ float  g_bnsq[2][FD];
__device__ unsigned int g_gmax[2][2];   // [layer][head]: encoded global max of asrc

__device__ __forceinline__ int clampN(int v) {
    return v < 0 ? 0 : (v >= NN ? NN - 1 : v);
}
__device__ __forceinline__ float lrelu(float v) { return v > 0.f ? v : NEG * v; }

// monotone float<->uint encoding for atomicMax
__device__ __forceinline__ unsigned int encf(float f) {
    unsigned int u = __float_as_uint(f);
    return (u & 0x80000000u) ? ~u : (u | 0x80000000u);
}
__device__ __forceinline__ float decf(unsigned int u) {
    return __uint_as_float((u & 0x80000000u) ? (u ^ 0x80000000u) : ~u);
}

__device__ __forceinline__ uint32_t f2tf32(float f) {
    uint32_t r;
    asm("cvt.rna.tf32.f32 %0, %1;" : "=r"(r) : "f"(f));
    return r;
}

#define MMA_TF32(d, a, b0, b1) \
    asm volatile("mma.sync.aligned.m16n8k8.row.col.f32.tf32.tf32.f32 " \
        "{%0,%1,%2,%3}, {%4,%5,%6,%7}, {%8,%9}, {%0,%1,%2,%3};" \
        : "+f"((d)[0]), "+f"((d)[1]), "+f"((d)[2]), "+f"((d)[3]) \
        : "r"((a)[0]), "r"((a)[1]), "r"((a)[2]), "r"((a)[3]), \
          "r"(b0), "r"(b1))

// -------- prep: zero counters/stats + precompute W tf32 hi/lo (both layers) ---
__global__ void k_prep(const float* __restrict__ W1, const float* __restrict__ W2) {
    int i = blockIdx.x * blockDim.x + threadIdx.x;
    if (i < NN) g_counts[i] = 0;
    if (i < FD) {
        g_bnsum[0][i] = 0.f; g_bnsq[0][i] = 0.f;
        g_bnsum[1][i] = 0.f; g_bnsq[1][i] = 0.f;
    }
    if (i < 4) g_gmax[i >> 1][i & 1] = 0u;
    if (i < FD * FD) {
        #pragma unroll
        for (int l = 0; l < 2; l++) {
            float w = (l ? W2 : W1)[i];
            uint32_t hb = f2tf32(w);
            float lof = w - __uint_as_float(hb);
            g_whi[l][i] = hb;
            g_wlo[l][i] = f2tf32(lof);
        }
    }
}

// ---------------- counting sort by destination --------------------------------
__global__ void k_hist(const int* __restrict__ dst) {
    int e4 = blockIdx.x * blockDim.x + threadIdx.x;
    if (e4 < EE / 4) {
        int4 d = ((const int4*)dst)[e4];
        atomicAdd(&g_counts[clampN(d.x)], 1);
        atomicAdd(&g_counts[clampN(d.y)], 1);
        atomicAdd(&g_counts[clampN(d.z)], 1);
        atomicAdd(&g_counts[clampN(d.w)], 1);
    }
}

__global__ void k_scan() {
    __shared__ int ssum[1024];
    const int CH = (NN + 1023) / 1024;
    int t = threadIdx.x;
    int base = t * CH;
    int s = 0;
    for (int i = 0; i < CH; i++) {
        int idx = base + i;
        if (idx < NN) s += g_counts[idx];
    }
    ssum[t] = s;
    __syncthreads();
    for (int o = 1; o < 1024; o <<= 1) {
        int u = (t >= o) ? ssum[t - o] : 0;
        __syncthreads();
        ssum[t] += u;
        __syncthreads();
    }
    int off = ssum[t] - s;
    for (int i = 0; i < CH; i++) {
        int idx = base + i;
        if (idx < NN) {
            g_offsets[idx] = off;
            g_cursor[idx]  = off;
            off += g_counts[idx];
        }
    }
    if (t == 0) g_offsets[NN] = EE;
}

__global__ void k_scatter(const int* __restrict__ src,
                          const int* __restrict__ dst) {
    int e4 = blockIdx.x * blockDim.x + threadIdx.x;
    if (e4 < EE / 4) {
        int4 d = ((const int4*)dst)[e4];
        int4 s = ((const int4*)src)[e4];
        int p;
        p = atomicAdd(&g_cursor[clampN(d.x)], 1); if (p >= 0 && p < EE) g_srt[p] = clampN(s.x);
        p = atomicAdd(&g_cursor[clampN(d.y)], 1); if (p >= 0 && p < EE) g_srt[p] = clampN(s.y);
        p = atomicAdd(&g_cursor[clampN(d.z)], 1); if (p >= 0 && p < EE) g_srt[p] = clampN(s.z);
        p = atomicAdd(&g_cursor[clampN(d.w)], 1); if (p >= 0 && p < EE) g_srt[p] = clampN(s.w);
    }
}

// ============== 3xTF32 mma.sync GEMM + attention-score epilogue ==============
// h stored to fp16 (half2) -> halves the aggregation gather traffic.
#define ASTR 20    // A row stride (conflict-free fragment access)
#define BSTR 136   // B k-row stride; 136 % 32 == 8 -> conflict-free
#define TF32_MASK 0xFFFFE000u

__global__ void k_gemm_mma(const float* __restrict__ X,
                           const float* __restrict__ gamma, const float* __restrict__ beta,
                           const float* __restrict__ att_s, const float* __restrict__ att_d,
                           int mode) {
    __shared__ uint32_t sAhi[128 * ASTR];
    __shared__ uint32_t sAlo[128 * ASTR];
    __shared__ uint32_t sBhi[16 * BSTR];
    __shared__ uint32_t sBlo[16 * BSTR];
    __shared__ float s_atts[FD], s_attd[FD], s_bnA[FD], s_bnB[FD];
    __shared__ unsigned int s_m0, s_m1;

    int t = threadIdx.x;
    int rb = blockIdx.x * 128;

    if (t == 0) { s_m0 = 0u; s_m1 = 0u; }
    if (t < FD) {
        s_atts[t] = att_s[t];
        s_attd[t] = att_d[t];
        if (mode) {
            float mean = g_bnsum[0][t] * (1.f / NN);
            float var  = g_bnsq[0][t] * (1.f / NN) - mean * mean;
            float a = gamma[t] * rsqrtf(var + BN_EPS);
            s_bnA[t] = a;
            s_bnB[t] = beta[t] - mean * a;
        }
    }

    int lane = t & 31, warp = t >> 5;
    int g  = lane >> 2;       // groupID (row within fragment)
    int t4 = lane & 3;        // threadID in group
    int wr = warp * 16;       // warp row base within tile

    float d[16][4];
    #pragma unroll
    for (int nt = 0; nt < 16; nt++) {
        d[nt][0] = 0.f; d[nt][1] = 0.f; d[nt][2] = 0.f; d[nt][3] = 0.f;
    }

    const float4* X4 = (const float4*)(mode ? (const float*)g_agg : X);
    const uint4* Whi4 = (const uint4*)g_whi[mode];
    const uint4* Wlo4 = (const uint4*)g_wlo[mode];

    for (int kc = 0; kc < 8; kc++) {
        __syncthreads();

        // --- stage A chunk: mask-based hi + exact residual lo ---
        #pragma unroll
        for (int j = 0; j < 2; j++) {
            int idx = t + j * 256;
            int row = idx >> 2, c4 = idx & 3;
            int grow = rb + row;
            float4 v = (grow < NN) ? X4[grow * 32 + kc * 4 + c4]
                                   : make_float4(0.f, 0.f, 0.f, 0.f);
            float vv[4] = {v.x, v.y, v.z, v.w};
            int sbase = row * ASTR + c4 * 4;
            #pragma unroll
            for (int i = 0; i < 4; i++) {
                float val = vv[i];
                if (mode) {
                    int c = kc * 16 + c4 * 4 + i;
                    float y = s_bnA[c] * val + s_bnB[c];
                    val = y > 0.f ? y : expm1f(y);
                }
                uint32_t hb = __float_as_uint(val) & TF32_MASK;
                float lof = val - __uint_as_float(hb);
                sAhi[sbase + i] = hb;
                sAlo[sbase + i] = __float_as_uint(lof) & TF32_MASK;
            }
        }

        // --- stage B chunk: pure copy of preconverted bits ---
        #pragma unroll
        for (int j = 0; j < 2; j++) {
            int idx = t + j * 256;
            int k = idx >> 5, c4 = idx & 31;
            uint4 h = Whi4[(kc * 16 + k) * 32 + c4];
            uint4 l = Wlo4[(kc * 16 + k) * 32 + c4];
            int sbase = k * BSTR + c4 * 4;
            sBhi[sbase + 0] = h.x; sBhi[sbase + 1] = h.y;
            sBhi[sbase + 2] = h.z; sBhi[sbase + 3] = h.w;
            sBlo[sbase + 0] = l.x; sBlo[sbase + 1] = l.y;
            sBlo[sbase + 2] = l.z; sBlo[sbase + 3] = l.w;
        }
        __syncthreads();

        #pragma unroll
        for (int ks = 0; ks < 2; ks++) {
            int kk = ks * 8;
            uint32_t ahi[4], alo[4];
            int ab = (wr + g) * ASTR + kk;
            ahi[0] = sAhi[ab + t4];
            ahi[1] = sAhi[ab + 8 * ASTR + t4];
            ahi[2] = sAhi[ab + t4 + 4];
            ahi[3] = sAhi[ab + 8 * ASTR + t4 + 4];
            alo[0] = sAlo[ab + t4];
            alo[1] = sAlo[ab + 8 * ASTR + t4];
            alo[2] = sAlo[ab + t4 + 4];
            alo[3] = sAlo[ab + 8 * ASTR + t4 + 4];
            #pragma unroll
            for (int nt = 0; nt < 16; nt++) {
                int bcol = nt * 8 + g;
                uint32_t bh0 = sBhi[(kk + t4) * BSTR + bcol];
                uint32_t bh1 = sBhi[(kk + t4 + 4) * BSTR + bcol];
                uint32_t bl0 = sBlo[(kk + t4) * BSTR + bcol];
                uint32_t bl1 = sBlo[(kk + t4 + 4) * BSTR + bcol];
                MMA_TF32(d[nt], ahi, bh0, bh1);
                MMA_TF32(d[nt], ahi, bl0, bl1);
                MMA_TF32(d[nt], alo, bh0, bh1);
            }
        }
    }

    // --- epilogue: store h (fp16), attention dots, block max of asrc ---
    int r0 = rb + wr + g;
    int r1 = r0 + 8;
    float ds0h0 = 0.f, ds0h1 = 0.f, dd0h0 = 0.f, dd0h1 = 0.f;
    float ds1h0 = 0.f, ds1h1 = 0.f, dd1h0 = 0.f, dd1h1 = 0.f;
    #pragma unroll
    for (int nt = 0; nt < 16; nt++) {
        int c0 = nt * 8 + t4 * 2;
        float a0 = s_atts[c0], a1 = s_atts[c0 + 1];
        float b0 = s_attd[c0], b1 = s_attd[c0 + 1];
        float p0 = d[nt][0] * a0 + d[nt][1] * a1;
        float q0 = d[nt][0] * b0 + d[nt][1] * b1;
        float p1 = d[nt][2] * a0 + d[nt][3] * a1;
        float q1 = d[nt][2] * b0 + d[nt][3] * b1;
        if (nt < 8) { ds0h0 += p0; dd0h0 += q0; ds1h0 += p1; dd1h0 += q1; }
        else        { ds0h1 += p0; dd0h1 += q0; ds1h1 += p1; dd1h1 += q1; }
        if (r0 < NN) {
            __half2 ph = __floats2half2_rn(d[nt][0], d[nt][1]);
            g_h2[r0 * 64 + (c0 >> 1)] = *(uint32_t*)&ph;
        }
        if (r1 < NN) {
            __half2 ph = __floats2half2_rn(d[nt][2], d[nt][3]);
            g_h2[r1 * 64 + (c0 >> 1)] = *(uint32_t*)&ph;
        }
    }
    #pragma unroll
    for (int o = 1; o <= 2; o <<= 1) {
        ds0h0 += __shfl_xor_sync(0xFFFFFFFFu, ds0h0, o);
        ds0h1 += __shfl_xor_sync(0xFFFFFFFFu, ds0h1, o);
        dd0h0 += __shfl_xor_sync(0xFFFFFFFFu, dd0h0, o);
        dd0h1 += __shfl_xor_sync(0xFFFFFFFFu, dd0h1, o);
        ds1h0 += __shfl_xor_sync(0xFFFFFFFFu, ds1h0, o);
        ds1h1 += __shfl_xor_sync(0xFFFFFFFFu, ds1h1, o);
        dd1h0 += __shfl_xor_sync(0xFFFFFFFFu, dd1h0, o);
        dd1h1 += __shfl_xor_sync(0xFFFFFFFFu, dd1h1, o);
    }
    if (t4 == 0) {
        if (r0 < NN) {
            g_asrc[r0] = make_float2(ds0h0, ds0h1);
            g_adst[r0] = make_float2(dd0h0, dd0h1);
            atomicMax(&s_m0, encf(ds0h0));
            atomicMax(&s_m1, encf(ds0h1));
        }
        if (r1 < NN) {
            g_asrc[r1] = make_float2(ds1h0, ds1h1);
            g_adst[r1] = make_float2(dd1h0, dd1h1);
            atomicMax(&s_m0, encf(ds1h0));
            atomicMax(&s_m1, encf(ds1h1));
        }
    }
    __syncthreads();
    if (t == 0) {
        atomicMax(&g_gmax[mode][0], s_m0);
        atomicMax(&g_gmax[mode][1], s_m1);
    }
}

// ----- warp-per-dst aggregation (fp16 h gather) + fused BN statistics --------
// grid is exactly NN/8 blocks x 8 warps: every warp owns one valid node.
__global__ void k_agg(const float* __restrict__ bias, int slot) {
    __shared__ int   s_src[8][64];
    __shared__ float s_a0[8][64];
    __shared__ float s_a1[8][64];
    __shared__ float s_red[8][128];
    int wb   = threadIdx.x >> 5;
    int lane = threadIdx.x & 31;
    int w = (blockIdx.x * blockDim.x + threadIdx.x) >> 5;
    int start = g_offsets[w];
    int deg   = g_offsets[w + 1] - start;

    float2 ad    = g_adst[w];
    float2 aself = g_asrc[w];
    float m0 = lrelu(decf(g_gmax[slot][0]) + ad.x);
    float m1 = lrelu(decf(g_gmax[slot][1]) + ad.y);

    // single pass: gather asrc, exp, stage (first 64 edges), accumulate sums
    float s0 = 0.f, s1 = 0.f;
    #pragma unroll
    for (int it = 0; it < 2; it++) {
        int j = it * 32 + lane;
        bool have = j < deg;
        int sj = 0;
        float x0 = 0.f, x1 = 0.f;
        if (have) {
            sj = g_srt[start + j];
            float2 a = g_asrc[sj];
            x0 = __expf(lrelu(a.x + ad.x) - m0);
            x1 = __expf(lrelu(a.y + ad.y) - m1);
        }
        s_src[wb][it * 32 + lane] = sj;
        s_a0[wb][it * 32 + lane] = x0;
        s_a1[wb][it * 32 + lane] = x1;
        s0 += x0; s1 += x1;
    }
    for (int j = 64 + lane; j < deg; j += 32) {   // astronomically rare tail
        float2 a = g_asrc[g_srt[start + j]];
        s0 += __expf(lrelu(a.x + ad.x) - m0);
        s1 += __expf(lrelu(a.y + ad.y) - m1);
    }
    #pragma unroll
    for (int o = 16; o; o >>= 1) {
        s0 += __shfl_xor_sync(0xFFFFFFFFu, s0, o);
        s1 += __shfl_xor_sync(0xFFFFFFFFu, s1, o);
    }
    float xs0 = __expf(lrelu(aself.x + ad.x) - m0);
    float xs1 = __expf(lrelu(aself.y + ad.y) - m1);
    s0 += xs0; s1 += xs1;
    float inv0 = 1.f / (s0 + 1e-16f);
    float inv1 = 1.f / (s1 + 1e-16f);

    // normalize own staged entries (lane-local), then make visible
    s_a0[wb][lane]      *= inv0;
    s_a0[wb][lane + 32] *= inv0;
    s_a1[wb][lane]      *= inv1;
    s_a1[wb][lane + 32] *= inv1;
    __syncwarp();

    int head = lane >> 4;
    const uint2* H2 = (const uint2*)g_h2;   // H2[row*32+lane] = ch 4l..4l+3

    float salpha = head ? xs1 * inv1 : xs0 * inv0;
    uint2 raw = H2[w * 32 + lane];
    float2 f01 = __half22float2(*(__half2*)&raw.x);
    float2 f23 = __half22float2(*(__half2*)&raw.y);
    float4 acc0 = make_float4(salpha * f01.x, salpha * f01.y,
                              salpha * f23.x, salpha * f23.y);
    float4 acc1 = make_float4(0.f, 0.f, 0.f, 0.f);
    float4 acc2 = make_float4(0.f, 0.f, 0.f, 0.f);
    float4 acc3 = make_float4(0.f, 0.f, 0.f, 0.f);

    const float* sal = head ? s_a1[wb] : s_a0[wb];
    int nd = deg < 64 ? deg : 64;
    int j = 0;
    for (; j + 3 < nd; j += 4) {     // quad accumulators -> 4x load MLP
        int i0 = s_src[wb][j],     i1 = s_src[wb][j + 1];
        int i2 = s_src[wb][j + 2], i3 = s_src[wb][j + 3];
        float a0 = sal[j],     a1 = sal[j + 1];
        float a2 = sal[j + 2], a3 = sal[j + 3];
        uint2 r0 = H2[i0 * 32 + lane];
        uint2 r1 = H2[i1 * 32 + lane];
        uint2 r2 = H2[i2 * 32 + lane];
        uint2 r3 = H2[i3 * 32 + lane];
        float2 p, q;
        p = __half22float2(*(__half2*)&r0.x); q = __half22float2(*(__half2*)&r0.y);
        acc0.x += a0 * p.x; acc0.y += a0 * p.y; acc0.z += a0 * q.x; acc0.w += a0 * q.y;
        p = __half22float2(*(__half2*)&r1.x); q = __half22float2(*(__half2*)&r1.y);
        acc1.x += a1 * p.x; acc1.y += a1 * p.y; acc1.z += a1 * q.x; acc1.w += a1 * q.y;
        p = __half22float2(*(__half2*)&r2.x); q = __half22float2(*(__half2*)&r2.y);
        acc2.x += a2 * p.x; acc2.y += a2 * p.y; acc2.z += a2 * q.x; acc2.w += a2 * q.y;
        p = __half22float2(*(__half2*)&r3.x); q = __half22float2(*(__half2*)&r3.y);
        acc3.x += a3 * p.x; acc3.y += a3 * p.y; acc3.z += a3 * q.x; acc3.w += a3 * q.y;
    }
    for (; j < nd; j++) {
        int sa = s_src[wb][j];
        float aa = sal[j];
        uint2 r = H2[sa * 32 + lane];
        float2 p = __half22float2(*(__half2*)&r.x);
        float2 q = __half22float2(*(__half2*)&r.y);
        acc0.x += aa * p.x; acc0.y += aa * p.y; acc0.z += aa * q.x; acc0.w += aa * q.y;
    }
    acc0.x += acc1.x + acc2.x + acc3.x;
    acc0.y += acc1.y + acc2.y + acc3.y;
    acc0.z += acc1.z + acc2.z + acc3.z;
    acc0.w += acc1.w + acc2.w + acc3.w;

    for (int jj = 64; jj < deg; jj++) {   // rare tail: recompute alpha inline
        int srcj = g_srt[start + jj];
        float2 a = g_asrc[srcj];
        float e = head ? (lrelu(a.y + ad.y) - m1) : (lrelu(a.x + ad.x) - m0);
        float alpha = __expf(e) * (head ? inv1 : inv0);
        uint2 r = H2[srcj * 32 + lane];
        float2 p = __half22float2(*(__half2*)&r.x);
        float2 q = __half22float2(*(__half2*)&r.y);
        acc0.x += alpha * p.x; acc0.y += alpha * p.y;
        acc0.z += alpha * q.x; acc0.w += alpha * q.y;
    }

    float4 b = ((const float4*)bias)[lane];
    acc0.x += b.x; acc0.y += b.y; acc0.z += b.z; acc0.w += b.w;
    ((float4*)g_agg)[w * 32 + lane] = acc0;

    // ---- fused BN statistics: block-reduce 8 rows, one atomic per column ----
    ((float4*)s_red[wb])[lane] = acc0;
    __syncthreads();
    int t = threadIdx.x;
    if (t < FD) {
        float sum = 0.f, sq = 0.f;
        #pragma unroll
        for (int b8 = 0; b8 < 8; b8++) {
            float v = s_red[b8][t];
            sum += v;
            sq = fmaf(v, v, sq);
        }
        atomicAdd(&g_bnsum[slot][t], sum);
        atomicAdd(&g_bnsq[slot][t],  sq);
    }
}

// ---------------- final BN+ELU -> out -----------------------------------------
__global__ void k_bnapply(const float* __restrict__ gamma,
                          const float* __restrict__ beta,
                          float* __restrict__ out) {
    int i = blockIdx.x * blockDim.x + threadIdx.x;
    if (i >= NN * 32) return;
    int c4 = (i & 31) * 4;
    float4 v  = ((const float4*)g_agg)[i];
    float4 gm = ((const float4*)gamma)[i & 31];
    float4 bt = ((const float4*)beta)[i & 31];
    float res[4];
    float vin[4] = {v.x, v.y, v.z, v.w};
    float gs[4]  = {gm.x, gm.y, gm.z, gm.w};
    float bs[4]  = {bt.x, bt.y, bt.z, bt.w};
    #pragma unroll
    for (int k = 0; k < 4; k++) {
        int c = c4 + k;
        float mean = g_bnsum[1][c] * (1.f / NN);
        float var  = g_bnsq[1][c] * (1.f / NN) - mean * mean;
        float is   = rsqrtf(var + BN_EPS);
        float y = (vin[k] - mean) * is * gs[k] + bs[k];
        res[k] = y > 0.f ? y : expm1f(y);
    }
    ((float4*)out)[i] = make_float4(res[0], res[1], res[2], res[3]);
}

// ---------------- launch: fork/join capture graph -----------------------------
// kernel_launch is called only for the correctness run and the single graph
// capture, so per-call stream/event creation (never destroyed) leaks a handful
// of host-side handles total, keeps work deterministic, and keeps the captured
// graph structure identical on every call.
extern "C" void kernel_launch(void* const* d_in, const int* in_sizes, int n_in,
                              void* d_out, int out_size) {
    const float* x        = (const float*)d_in[0];
    const int*   eidx     = (const int*)d_in[1];
    const float* W1       = (const float*)d_in[2];
    const float* att_src1 = (const float*)d_in[3];
    const float* att_dst1 = (const float*)d_in[4];
    const float* b1       = (const float*)d_in[5];
    const float* W2       = (const float*)d_in[6];
    const float* att_src2 = (const float*)d_in[7];
    const float* att_dst2 = (const float*)d_in[8];
    const float* b2       = (const float*)d_in[9];
    const float* g1       = (const float*)d_in[10];
    const float* be1      = (const float*)d_in[11];
    const float* g2       = (const float*)d_in[12];
    const float* be2      = (const float*)d_in[13];
    float* out = (float*)d_out;

    const int* esrc = eidx;
    const int* edst = eidx + EE;

    const int WARP_BLOCKS = NN / 8;                 // 6250 (exact)
    const int MMA_BLOCKS  = (NN + 127) / 128;       // 391
    const int E4_BLOCKS   = (EE / 4 + 255) / 256;

    cudaStream_t side;
    cudaEvent_t ev_fork, ev_join;
    cudaStreamCreateWithFlags(&side, cudaStreamNonBlocking);
    cudaEventCreateWithFlags(&ev_fork, cudaEventDisableTiming);
    cudaEventCreateWithFlags(&ev_join, cudaEventDisableTiming);

    // prep (zeros counts + converts W) on main stream
    k_prep<<<(NN + 255) / 256, 256>>>(W1, W2);

    // fork: CSR build on side stream, concurrent with layer-1 GEMM on main
    cudaEventRecord(ev_fork, 0);
    cudaStreamWaitEvent(side, ev_fork, 0);
    k_hist<<<E4_BLOCKS, 256, 0, side>>>(edst);
    k_scan<<<1, 1024, 0, side>>>();
    k_scatter<<<E4_BLOCKS, 256, 0, side>>>(esrc, edst);
    cudaEventRecord(ev_join, side);

    k_gemm_mma<<<MMA_BLOCKS, 256>>>(x, g1, be1, att_src1, att_dst1, 0);

    // join: aggregation needs both GEMM output and the CSR
    cudaStreamWaitEvent(0, ev_join, 0);
    k_agg<<<WARP_BLOCKS, 256>>>(b1, 0);

    // --- layer 2 (BN+ELU of layer 1 fused into A-load; stats fused into agg) ---
    k_gemm_mma<<<MMA_BLOCKS, 256>>>(x, g2, be2, att_src2, att_dst2, 1);
    k_agg<<<WARP_BLOCKS, 256>>>(b2, 1);
    k_bnapply<<<WARP_BLOCKS, 256>>>(g2, be2, out);
}